// round 1
// baseline (speedup 1.0000x reference)
#include <cuda_runtime.h>
#include <math.h>

// Problem config
#define E_   1024
#define H_   16
#define D_   64
#define L_   6
#define FF_  4096
#define B_   4
#define T_   1024
#define BT_  4096
#define V_   32000

// Scratch (device globals — allocation-free per harness rules)
__device__ float g_x[BT_ * E_];
__device__ float g_h[BT_ * E_];
__device__ float g_q[H_ * BT_ * D_];
__device__ float g_k[H_ * BT_ * D_];
__device__ float g_v[H_ * BT_ * D_];
__device__ float g_s[(size_t)B_ * H_ * T_ * T_];   // 256 MB attention scores
__device__ float g_o[H_ * BT_ * D_];
__device__ float g_oc[BT_ * E_];
__device__ float g_ff[BT_ * FF_];
__device__ float g_rl[BT_];

// flags
#define FLAG_TRANSB   1   // B accessed as [N,K]
#define FLAG_MASK     2   // causal mask + scale in epilogue
#define FLAG_RELU     4
#define FLAG_CAUSAL_A 8   // A is causal probs: break K loop past diagonal

// ---------------------------------------------------------------------------
// Generic batched SGEMM: C = epilogue(A @ B)
// 128x128 block tile, BK=8, 256 threads, 8x8 per-thread micro tile.
// ---------------------------------------------------------------------------
__global__ __launch_bounds__(256)
void sgemm_kernel(const float* __restrict__ A, int lda, long long sA,
                  const float* __restrict__ Bm, int ldb, long long sB,
                  float* __restrict__ C, int ldc, long long sC,
                  int M, int N, int K,
                  const float* __restrict__ bias,
                  const float* __restrict__ resid, int ldr, long long sR,
                  int flags, float scale)
{
    const int z = blockIdx.z;
    A  += (long long)z * sA;
    Bm += (long long)z * sB;
    C  += (long long)z * sC;
    if (resid) resid += (long long)z * sR;

    const int row0 = blockIdx.y * 128;
    const int col0 = blockIdx.x * 128;
    const int tid  = threadIdx.x;
    const int tr   = (tid >> 4) * 8;   // thread row base (0..120)
    const int tc   = (tid & 15) * 8;   // thread col base (0..120)

    __shared__ float As[8][128];
    __shared__ float Bs[8][128];

    float acc[8][8];
#pragma unroll
    for (int i = 0; i < 8; i++)
#pragma unroll
        for (int j = 0; j < 8; j++) acc[i][j] = 0.f;

    // fully-masked score tile: skip all compute, epilogue writes -inf
    const bool fullmask = ((flags & FLAG_MASK) != 0) && (col0 > row0 + 127);

    if (!fullmask) {
        for (int k0 = 0; k0 < K; k0 += 8) {
            if ((flags & FLAG_CAUSAL_A) && (k0 > row0 + 127)) break;
            // load A tile [128 x 8] transposed into As[k][m]
#pragma unroll
            for (int i = 0; i < 4; i++) {
                int e  = tid + i * 256;       // 0..1023
                int r  = e >> 3, kk = e & 7;
                int gr = row0 + r, gk = k0 + kk;
                As[kk][r] = (gr < M && gk < K) ? A[(long long)gr * lda + gk] : 0.f;
            }
            // load B tile [8 x 128] into Bs[k][n]
#pragma unroll
            for (int i = 0; i < 4; i++) {
                int e  = tid + i * 256;
                int kk = e >> 7, c = e & 127;
                int gc = col0 + c, gk = k0 + kk;
                float vb = 0.f;
                if (gc < N && gk < K)
                    vb = (flags & FLAG_TRANSB) ? Bm[(long long)gc * ldb + gk]
                                               : Bm[(long long)gk * ldb + gc];
                Bs[kk][c] = vb;
            }
            __syncthreads();
#pragma unroll
            for (int kk = 0; kk < 8; kk++) {
                float a[8], b[8];
#pragma unroll
                for (int i = 0; i < 8; i++) a[i] = As[kk][tr + i];
#pragma unroll
                for (int j = 0; j < 8; j++) b[j] = Bs[kk][tc + j];
#pragma unroll
                for (int i = 0; i < 8; i++)
#pragma unroll
                    for (int j = 0; j < 8; j++) acc[i][j] += a[i] * b[j];
            }
            __syncthreads();
        }
    }

    // epilogue
#pragma unroll
    for (int i = 0; i < 8; i++) {
        int r = row0 + tr + i;
        if (r >= M) continue;
#pragma unroll
        for (int j = 0; j < 8; j++) {
            int c = col0 + tc + j;
            if (c >= N) continue;
            float vv = acc[i][j];
            if (flags & FLAG_MASK) vv = (c <= r) ? vv * scale : -1e30f;
            if (bias)  vv += bias[c];
            if (resid) vv += resid[(long long)r * ldr + c];
            if (flags & FLAG_RELU) vv = fmaxf(vv, 0.f);
            C[(long long)r * ldc + c] = vv;
        }
    }
}

// ---------------------------------------------------------------------------
// Embedding: x[b,t,:] = tok_emb[idx[b,t],:] + pos_emb[t,:]
// ---------------------------------------------------------------------------
__global__ void embed_kernel(const int* __restrict__ idx,
                             const float* __restrict__ tok,
                             const float* __restrict__ pos,
                             float* __restrict__ x)
{
    int row = blockIdx.x;           // 0..BT-1
    int t   = row & (T_ - 1);
    int tk  = idx[row];
    const float* te = tok + (long long)tk * E_;
    const float* pe = pos + (long long)t  * E_;
    float* xr = x + (long long)row * E_;
    for (int c = threadIdx.x; c < E_; c += blockDim.x)
        xr[c] = te[c] + pe[c];
}

// ---------------------------------------------------------------------------
// LayerNorm over E=1024, 256 threads/row
// ---------------------------------------------------------------------------
__global__ void ln_kernel(const float* __restrict__ x, float* __restrict__ y,
                          const float* __restrict__ sc, const float* __restrict__ bi)
{
    int row = blockIdx.x;
    const float* xr = x + (long long)row * E_;
    float* yr = y + (long long)row * E_;
    float v[4];
    float sum = 0.f, sq = 0.f;
#pragma unroll
    for (int i = 0; i < 4; i++) {
        v[i] = xr[threadIdx.x + i * 256];
        sum += v[i]; sq += v[i] * v[i];
    }
    __shared__ float s1[256], s2[256];
    s1[threadIdx.x] = sum; s2[threadIdx.x] = sq;
    __syncthreads();
    for (int st = 128; st > 0; st >>= 1) {
        if (threadIdx.x < st) {
            s1[threadIdx.x] += s1[threadIdx.x + st];
            s2[threadIdx.x] += s2[threadIdx.x + st];
        }
        __syncthreads();
    }
    float mean = s1[0] * (1.f / E_);
    float var  = s2[0] * (1.f / E_) - mean * mean;
    float inv  = rsqrtf(var + 1e-5f);
#pragma unroll
    for (int i = 0; i < 4; i++) {
        int c = threadIdx.x + i * 256;
        yr[c] = (v[i] - mean) * inv * sc[c] + bi[c];
    }
}

// ---------------------------------------------------------------------------
// Row softmax over T=1024 (masked entries are -1e30 -> exp()=0)
// ---------------------------------------------------------------------------
__global__ void softmax_kernel(float* __restrict__ s)
{
    long long row = blockIdx.x;
    float* r = s + row * T_;
    float v[4];
    float m = -1e30f;
#pragma unroll
    for (int i = 0; i < 4; i++) {
        v[i] = r[threadIdx.x + i * 256];
        m = fmaxf(m, v[i]);
    }
    __shared__ float sm[256];
    sm[threadIdx.x] = m; __syncthreads();
    for (int st = 128; st > 0; st >>= 1) {
        if (threadIdx.x < st) sm[threadIdx.x] = fmaxf(sm[threadIdx.x], sm[threadIdx.x + st]);
        __syncthreads();
    }
    m = sm[0];
    __syncthreads();
    float sum = 0.f;
#pragma unroll
    for (int i = 0; i < 4; i++) { v[i] = expf(v[i] - m); sum += v[i]; }
    sm[threadIdx.x] = sum; __syncthreads();
    for (int st = 128; st > 0; st >>= 1) {
        if (threadIdx.x < st) sm[threadIdx.x] += sm[threadIdx.x + st];
        __syncthreads();
    }
    float inv = 1.f / sm[0];
#pragma unroll
    for (int i = 0; i < 4; i++) r[threadIdx.x + i * 256] = v[i] * inv;
}

// ---------------------------------------------------------------------------
// Merge heads: oc[(b*T+t)*E + h*D + d] = o[((h*B+b)*T + t)*D + d]
// ---------------------------------------------------------------------------
__global__ void merge_heads_kernel(const float* __restrict__ o, float* __restrict__ oc)
{
    int g = blockIdx.x * 256 + threadIdx.x;   // 0 .. BT*E-1
    int c = g & (E_ - 1);
    int m = g >> 10;
    int h = c >> 6, d = c & 63;
    int b = m >> 10, t = m & (T_ - 1);
    oc[g] = o[((((long long)h * B_ + b) * T_ + t) << 6) + d];
}

// ---------------------------------------------------------------------------
// Per-row weighted CE (online LSE over V=32000)
// ---------------------------------------------------------------------------
__global__ void loss_rows_kernel(const float* __restrict__ logits,
                                 const int* __restrict__ tgt,
                                 float* __restrict__ rl)
{
    int row = blockIdx.x;
    const float* lg = logits + (long long)row * V_;
    int tid = threadIdx.x;
    float m = -1e30f, s = 0.f;
    for (int c = tid; c < V_; c += 256) {
        float x = lg[c];
        float nm = fmaxf(m, x);
        s = s * expf(m - nm) + expf(x - nm);
        m = nm;
    }
    __shared__ float sm[256], ss[256];
    sm[tid] = m; ss[tid] = s;
    __syncthreads();
    for (int st = 128; st > 0; st >>= 1) {
        if (tid < st) {
            float m2 = sm[tid + st], s2 = ss[tid + st];
            float nm = fmaxf(sm[tid], m2);
            ss[tid] = ss[tid] * expf(sm[tid] - nm) + s2 * expf(m2 - nm);
            sm[tid] = nm;
        }
        __syncthreads();
    }
    if (tid == 0) {
        float lse = sm[0] + logf(ss[0]);
        int t = tgt[row];
        float ce = lse - lg[t];
        float w = 1.f;
        if (t == 4 || t == 3 || t == 1) w = 1.5f;   // CTX | QUES | SQL
        if (t == 2) w = 2.0f;                        // EOS
        if (t == 0) w = 0.1f;                        // PAD
        rl[row] = ce * w;
    }
}

__global__ void loss_reduce_kernel(const float* __restrict__ rl, float* __restrict__ out)
{
    __shared__ float sm[1024];
    float s = 0.f;
    for (int i = threadIdx.x; i < BT_; i += 1024) s += rl[i];
    sm[threadIdx.x] = s;
    __syncthreads();
    for (int st = 512; st > 0; st >>= 1) {
        if (threadIdx.x < st) sm[threadIdx.x] += sm[threadIdx.x + st];
        __syncthreads();
    }
    if (threadIdx.x == 0) *out = sm[0] * (1.f / BT_);
}

// ---------------------------------------------------------------------------
// Host driver
// ---------------------------------------------------------------------------
static inline void gemm(const float* A, int lda, long long sA,
                        const float* Bm, int ldb, long long sB,
                        float* C, int ldc, long long sC,
                        int M, int N, int K, int batch,
                        const float* bias, const float* resid, int ldr, long long sR,
                        int flags, float scale)
{
    dim3 grid((N + 127) / 128, (M + 127) / 128, batch);
    sgemm_kernel<<<grid, 256>>>(A, lda, sA, Bm, ldb, sB, C, ldc, sC,
                                M, N, K, bias, resid, ldr, sR, flags, scale);
}

extern "C" void kernel_launch(void* const* d_in, const int* in_sizes, int n_in,
                              void* d_out, int out_size)
{
    const int*   idx = (const int*)d_in[0];
    const int*   tgt = (const int*)d_in[1];
    const float* tok = (const float*)d_in[2];
    const float* pos = (const float*)d_in[3];
    const float* Wq  = (const float*)d_in[4];
    const float* Wk  = (const float*)d_in[5];
    const float* Wv  = (const float*)d_in[6];
    const float* Wp  = (const float*)d_in[7];
    const float* bp  = (const float*)d_in[8];
    const float* W1  = (const float*)d_in[9];
    const float* b1  = (const float*)d_in[10];
    const float* W2  = (const float*)d_in[11];
    const float* b2  = (const float*)d_in[12];
    const float* l1s = (const float*)d_in[13];
    const float* l1b = (const float*)d_in[14];
    const float* l2s = (const float*)d_in[15];
    const float* l2b = (const float*)d_in[16];
    const float* lfs = (const float*)d_in[17];
    const float* lfb = (const float*)d_in[18];
    const float* Wh  = (const float*)d_in[19];
    const float* bh  = (const float*)d_in[20];
    float* out = (float*)d_out;

    float *x, *h, *q, *k, *v, *s, *o, *oc, *ff, *rl;
    cudaGetSymbolAddress((void**)&x,  g_x);
    cudaGetSymbolAddress((void**)&h,  g_h);
    cudaGetSymbolAddress((void**)&q,  g_q);
    cudaGetSymbolAddress((void**)&k,  g_k);
    cudaGetSymbolAddress((void**)&v,  g_v);
    cudaGetSymbolAddress((void**)&s,  g_s);
    cudaGetSymbolAddress((void**)&o,  g_o);
    cudaGetSymbolAddress((void**)&oc, g_oc);
    cudaGetSymbolAddress((void**)&ff, g_ff);
    cudaGetSymbolAddress((void**)&rl, g_rl);

    // Embedding
    embed_kernel<<<BT_, 256>>>(idx, tok, pos, x);

    const long long hW  = (long long)E_ * D_;        // per-head weight stride
    const long long qS  = (long long)BT_ * D_;       // per-head q/k/v stride
    const long long aS  = (long long)T_ * D_;        // per-(b,h) q/k/v stride
    const long long sS  = (long long)T_ * T_;        // per-(b,h) score stride

    for (int l = 0; l < L_; l++) {
        // LN1
        ln_kernel<<<BT_, 256>>>(x, h, l1s + l * E_, l1b + l * E_);

        // QKV (batched over 16 heads): [BT,E] @ [E,D] -> [H, BT, D]
        gemm(h, E_, 0, Wq + (long long)l * H_ * hW, D_, hW, q, D_, qS,
             BT_, D_, E_, H_, nullptr, nullptr, 0, 0, 0, 0.f);
        gemm(h, E_, 0, Wk + (long long)l * H_ * hW, D_, hW, k, D_, qS,
             BT_, D_, E_, H_, nullptr, nullptr, 0, 0, 0, 0.f);
        gemm(h, E_, 0, Wv + (long long)l * H_ * hW, D_, hW, v, D_, qS,
             BT_, D_, E_, H_, nullptr, nullptr, 0, 0, 0, 0.f);

        // Scores: S = mask(Q @ K^T * E^-0.5), batched over 64 (b,h)
        gemm(q, D_, aS, k, D_, aS, s, T_, sS,
             T_, T_, D_, B_ * H_, nullptr, nullptr, 0, 0,
             FLAG_TRANSB | FLAG_MASK, 0.03125f /* 1/sqrt(1024) */);

        // Softmax
        softmax_kernel<<<B_ * H_ * T_, 256>>>(s);

        // O = P @ V (K-loop early-exits past the causal diagonal)
        gemm(s, T_, sS, v, D_, aS, o, D_, aS,
             T_, D_, T_, B_ * H_, nullptr, nullptr, 0, 0, FLAG_CAUSAL_A, 0.f);

        // Concat heads
        merge_heads_kernel<<<(BT_ * E_) / 256, 256>>>(o, oc);

        // x = x + O @ Wproj + bproj
        gemm(oc, E_, 0, Wp + (long long)l * E_ * E_, E_, 0, x, E_, 0,
             BT_, E_, E_, 1, bp + l * E_, x, E_, 0, 0, 0.f);

        // LN2
        ln_kernel<<<BT_, 256>>>(x, h, l2s + l * E_, l2b + l * E_);

        // ff = relu(h @ W1 + b1)
        gemm(h, E_, 0, W1 + (long long)l * E_ * FF_, FF_, 0, ff, FF_, 0,
             BT_, FF_, E_, 1, b1 + l * FF_, nullptr, 0, 0, FLAG_RELU, 0.f);

        // x = x + ff @ W2 + b2
        gemm(ff, FF_, 0, W2 + (long long)l * FF_ * E_, E_, 0, x, E_, 0,
             BT_, E_, FF_, 1, b2 + l * E_, x, E_, 0, 0, 0.f);
    }

    // Final LN + head
    ln_kernel<<<BT_, 256>>>(x, h, lfs, lfb);
    gemm(h, E_, 0, Wh, V_, 0, out, V_, 0,
         BT_, V_, E_, 1, bh, nullptr, 0, 0, 0, 0.f);

    // Weighted CE loss -> out[BT*V]
    loss_rows_kernel<<<BT_, 256>>>(out, tgt, rl);
    if ((long long)out_size >= (long long)BT_ * V_ + 1)
        loss_reduce_kernel<<<1, 1024>>>(rl, out + (long long)BT_ * V_);
}

// round 2
// speedup vs baseline: 4.5932x; 4.5932x over previous
#include <cuda_runtime.h>
#include <math.h>
#include <stdint.h>

// Problem config
#define E_   1024
#define H_   16
#define D_   64
#define L_   6
#define FF_  4096
#define B_   4
#define T_   1024
#define BT_  4096
#define V_   32000

// Scratch (device globals — allocation-free per harness rules)
__device__ __align__(16) float g_x[BT_ * E_];
__device__ __align__(16) float g_h[BT_ * E_];
__device__ __align__(16) float g_q[H_ * BT_ * D_];
__device__ __align__(16) float g_k[H_ * BT_ * D_];
__device__ __align__(16) float g_v[H_ * BT_ * D_];
__device__ __align__(16) float g_s[(size_t)B_ * H_ * T_ * T_];   // 256 MB scores
__device__ __align__(16) float g_o[H_ * BT_ * D_];
__device__ __align__(16) float g_oc[BT_ * E_];
__device__ __align__(16) float g_ff[BT_ * FF_];
__device__ __align__(16) float g_rl[BT_];

// flags
#define FLAG_TRANSB   1   // B accessed as [N,K]
#define FLAG_MASK     2   // causal mask + scale in epilogue
#define FLAG_RELU     4
#define FLAG_CAUSAL_A 8   // A is causal probs: break K loop past diagonal

__device__ __forceinline__ uint32_t f2tf(float f) {
    uint32_t u;
    asm("cvt.rna.tf32.f32 %0, %1;" : "=r"(u) : "f"(f));
    return u;
}

// ---------------------------------------------------------------------------
// tf32 tensor-core GEMM: C = epilogue(A @ B), fp32 accumulate.
// BM x BN block tile, BK=32, warp tile (BM/WARPS_M) x (BN/WARPS_N).
// All dims assumed multiples of tile sizes (true for this problem).
// ---------------------------------------------------------------------------
template<int BM, int BN, int WARPS_M, int WARPS_N>
__global__ __launch_bounds__(WARPS_M * WARPS_N * 32)
void mma_gemm(const float* __restrict__ A, int lda, long long sA,
              const float* __restrict__ Bm, int ldb, long long sB,
              float* __restrict__ C, int ldc, long long sC,
              int M, int N, int K,
              const float* __restrict__ bias,
              const float* __restrict__ resid, int ldr, long long sR,
              int flags, float scale)
{
    constexpr int BK = 32;
    constexpr int NT = WARPS_M * WARPS_N * 32;
    constexpr int WM = BM / WARPS_M;
    constexpr int WN = BN / WARPS_N;
    constexpr int MI = WM / 16;
    constexpr int NI = WN / 8;
    constexpr int AST = BK + 4;     // A smem stride ([m][k])
    constexpr int BSTN = BN + 8;    // B smem stride ([k][n]) non-trans
    constexpr int BS_ELEMS = (BK * BSTN > BN * AST) ? BK * BSTN : BN * AST;

    __shared__ uint32_t As[BM * AST];
    __shared__ uint32_t Bs[BS_ELEMS];

    const int z = blockIdx.z;
    A  += (long long)z * sA;
    Bm += (long long)z * sB;
    C  += (long long)z * sC;
    if (resid) resid += (long long)z * sR;

    const int row0 = blockIdx.y * BM;
    const int col0 = blockIdx.x * BN;
    const int tid  = threadIdx.x;
    const int warp = tid >> 5;
    const int lane = tid & 31;
    const int wm   = (warp / WARPS_N) * WM;
    const int wn   = (warp % WARPS_N) * WN;
    const int qr   = lane >> 2;    // group id
    const int qc   = lane & 3;     // thread-in-group

    float acc[MI][NI][4];
#pragma unroll
    for (int i = 0; i < MI; i++)
#pragma unroll
        for (int j = 0; j < NI; j++)
#pragma unroll
            for (int t = 0; t < 4; t++) acc[i][j][t] = 0.f;

    const bool transB   = (flags & FLAG_TRANSB) != 0;
    const bool fullmask = ((flags & FLAG_MASK) != 0) && (col0 > row0 + BM - 1);

    if (!fullmask) {
        for (int k0 = 0; k0 < K; k0 += BK) {
            if ((flags & FLAG_CAUSAL_A) && (k0 > row0 + BM - 1)) break;
            __syncthreads();
            // ---- load A tile [BM x BK] as [m][k], float4 along K ----
            constexpr int AV = BM * BK / 4 / NT;   // float4 per thread
#pragma unroll
            for (int i = 0; i < AV; i++) {
                int e  = tid + i * NT;
                int m  = e / (BK / 4);
                int kq = e % (BK / 4);
                const float4 f = *(const float4*)(A + (long long)(row0 + m) * lda + k0 + kq * 4);
                uint32_t* p = &As[m * AST + kq * 4];
                p[0] = f2tf(f.x); p[1] = f2tf(f.y); p[2] = f2tf(f.z); p[3] = f2tf(f.w);
            }
            // ---- load B tile ----
            if (transB) {
                // B is [N,K]; store as [n][k]
                constexpr int BV = BN * BK / 4 / NT;
#pragma unroll
                for (int i = 0; i < BV; i++) {
                    int e  = tid + i * NT;
                    int n  = e / (BK / 4);
                    int kq = e % (BK / 4);
                    const float4 f = *(const float4*)(Bm + (long long)(col0 + n) * ldb + k0 + kq * 4);
                    uint32_t* p = &Bs[n * AST + kq * 4];
                    p[0] = f2tf(f.x); p[1] = f2tf(f.y); p[2] = f2tf(f.z); p[3] = f2tf(f.w);
                }
            } else {
                // B is [K,N]; store as [k][n]
                constexpr int BV = BK * BN / 4 / NT;
#pragma unroll
                for (int i = 0; i < BV; i++) {
                    int e  = tid + i * NT;
                    int kk = e / (BN / 4);
                    int nq = e % (BN / 4);
                    const float4 f = *(const float4*)(Bm + (long long)(k0 + kk) * ldb + col0 + nq * 4);
                    uint32_t* p = &Bs[kk * BSTN + nq * 4];
                    p[0] = f2tf(f.x); p[1] = f2tf(f.y); p[2] = f2tf(f.z); p[3] = f2tf(f.w);
                }
            }
            __syncthreads();

            // ---- compute: 4 k8 sub-steps ----
#pragma unroll
            for (int kk = 0; kk < BK; kk += 8) {
                uint32_t a[MI][4];
#pragma unroll
                for (int mi = 0; mi < MI; mi++) {
                    int r = wm + mi * 16 + qr;
                    a[mi][0] = As[r * AST + kk + qc];
                    a[mi][1] = As[(r + 8) * AST + kk + qc];
                    a[mi][2] = As[r * AST + kk + qc + 4];
                    a[mi][3] = As[(r + 8) * AST + kk + qc + 4];
                }
                uint32_t b[NI][2];
#pragma unroll
                for (int ni = 0; ni < NI; ni++) {
                    int n = wn + ni * 8 + qr;
                    if (transB) {
                        b[ni][0] = Bs[n * AST + kk + qc];
                        b[ni][1] = Bs[n * AST + kk + qc + 4];
                    } else {
                        b[ni][0] = Bs[(kk + qc) * BSTN + n];
                        b[ni][1] = Bs[(kk + qc + 4) * BSTN + n];
                    }
                }
#pragma unroll
                for (int mi = 0; mi < MI; mi++)
#pragma unroll
                    for (int ni = 0; ni < NI; ni++) {
                        asm volatile(
                            "mma.sync.aligned.m16n8k8.row.col.f32.tf32.tf32.f32 "
                            "{%0,%1,%2,%3}, {%4,%5,%6,%7}, {%8,%9}, {%0,%1,%2,%3};\n"
                            : "+f"(acc[mi][ni][0]), "+f"(acc[mi][ni][1]),
                              "+f"(acc[mi][ni][2]), "+f"(acc[mi][ni][3])
                            : "r"(a[mi][0]), "r"(a[mi][1]), "r"(a[mi][2]), "r"(a[mi][3]),
                              "r"(b[ni][0]), "r"(b[ni][1]));
                    }
            }
        }
    }

    // ---- epilogue ----
#pragma unroll
    for (int mi = 0; mi < MI; mi++) {
#pragma unroll
        for (int ni = 0; ni < NI; ni++) {
#pragma unroll
            for (int t = 0; t < 4; t++) {
                int r = row0 + wm + mi * 16 + qr + ((t >= 2) ? 8 : 0);
                int c = col0 + wn + ni * 8 + qc * 2 + (t & 1);
                float vv = acc[mi][ni][t];
                if (flags & FLAG_MASK) vv = (c <= r) ? vv * scale : -1e30f;
                if (bias)  vv += bias[c];
                if (resid) vv += resid[(long long)r * ldr + c];
                if (flags & FLAG_RELU) vv = fmaxf(vv, 0.f);
                C[(long long)r * ldc + c] = vv;
            }
        }
    }
}

// ---------------------------------------------------------------------------
// Embedding
// ---------------------------------------------------------------------------
__global__ void embed_kernel(const int* __restrict__ idx,
                             const float* __restrict__ tok,
                             const float* __restrict__ pos,
                             float* __restrict__ x)
{
    int row = blockIdx.x;
    int t   = row & (T_ - 1);
    int tk  = idx[row];
    const float* te = tok + (long long)tk * E_;
    const float* pe = pos + (long long)t  * E_;
    float* xr = x + (long long)row * E_;
    for (int c = threadIdx.x; c < E_; c += blockDim.x)
        xr[c] = te[c] + pe[c];
}

// ---------------------------------------------------------------------------
// LayerNorm over E=1024
// ---------------------------------------------------------------------------
__global__ void ln_kernel(const float* __restrict__ x, float* __restrict__ y,
                          const float* __restrict__ sc, const float* __restrict__ bi)
{
    int row = blockIdx.x;
    const float* xr = x + (long long)row * E_;
    float* yr = y + (long long)row * E_;
    float v[4];
    float sum = 0.f, sq = 0.f;
#pragma unroll
    for (int i = 0; i < 4; i++) {
        v[i] = xr[threadIdx.x + i * 256];
        sum += v[i]; sq += v[i] * v[i];
    }
    __shared__ float s1[256], s2[256];
    s1[threadIdx.x] = sum; s2[threadIdx.x] = sq;
    __syncthreads();
    for (int st = 128; st > 0; st >>= 1) {
        if (threadIdx.x < st) {
            s1[threadIdx.x] += s1[threadIdx.x + st];
            s2[threadIdx.x] += s2[threadIdx.x + st];
        }
        __syncthreads();
    }
    float mean = s1[0] * (1.f / E_);
    float var  = s2[0] * (1.f / E_) - mean * mean;
    float inv  = rsqrtf(var + 1e-5f);
#pragma unroll
    for (int i = 0; i < 4; i++) {
        int c = threadIdx.x + i * 256;
        yr[c] = (v[i] - mean) * inv * sc[c] + bi[c];
    }
}

// ---------------------------------------------------------------------------
// Row softmax over T=1024
// ---------------------------------------------------------------------------
__global__ void softmax_kernel(float* __restrict__ s)
{
    long long row = blockIdx.x;
    float* r = s + row * T_;
    float v[4];
    float m = -1e30f;
#pragma unroll
    for (int i = 0; i < 4; i++) {
        v[i] = r[threadIdx.x + i * 256];
        m = fmaxf(m, v[i]);
    }
    __shared__ float sm[256];
    sm[threadIdx.x] = m; __syncthreads();
    for (int st = 128; st > 0; st >>= 1) {
        if (threadIdx.x < st) sm[threadIdx.x] = fmaxf(sm[threadIdx.x], sm[threadIdx.x + st]);
        __syncthreads();
    }
    m = sm[0];
    __syncthreads();
    float sum = 0.f;
#pragma unroll
    for (int i = 0; i < 4; i++) { v[i] = expf(v[i] - m); sum += v[i]; }
    sm[threadIdx.x] = sum; __syncthreads();
    for (int st = 128; st > 0; st >>= 1) {
        if (threadIdx.x < st) sm[threadIdx.x] += sm[threadIdx.x + st];
        __syncthreads();
    }
    float inv = 1.f / sm[0];
#pragma unroll
    for (int i = 0; i < 4; i++) r[threadIdx.x + i * 256] = v[i] * inv;
}

// ---------------------------------------------------------------------------
// Merge heads
// ---------------------------------------------------------------------------
__global__ void merge_heads_kernel(const float* __restrict__ o, float* __restrict__ oc)
{
    int g = blockIdx.x * 256 + threadIdx.x;
    int c = g & (E_ - 1);
    int m = g >> 10;
    int h = c >> 6, d = c & 63;
    int b = m >> 10, t = m & (T_ - 1);
    oc[g] = o[((((long long)h * B_ + b) * T_ + t) << 6) + d];
}

// ---------------------------------------------------------------------------
// Per-row weighted CE
// ---------------------------------------------------------------------------
__global__ void loss_rows_kernel(const float* __restrict__ logits,
                                 const int* __restrict__ tgt,
                                 float* __restrict__ rl)
{
    int row = blockIdx.x;
    const float* lg = logits + (long long)row * V_;
    int tid = threadIdx.x;
    float m = -1e30f, s = 0.f;
    for (int c = tid; c < V_; c += 256) {
        float x = lg[c];
        float nm = fmaxf(m, x);
        s = s * expf(m - nm) + expf(x - nm);
        m = nm;
    }
    __shared__ float sm[256], ss[256];
    sm[tid] = m; ss[tid] = s;
    __syncthreads();
    for (int st = 128; st > 0; st >>= 1) {
        if (tid < st) {
            float m2 = sm[tid + st], s2 = ss[tid + st];
            float nm = fmaxf(sm[tid], m2);
            ss[tid] = ss[tid] * expf(sm[tid] - nm) + s2 * expf(m2 - nm);
            sm[tid] = nm;
        }
        __syncthreads();
    }
    if (tid == 0) {
        float lse = sm[0] + logf(ss[0]);
        int t = tgt[row];
        float ce = lse - lg[t];
        float w = 1.f;
        if (t == 4 || t == 3 || t == 1) w = 1.5f;
        if (t == 2) w = 2.0f;
        if (t == 0) w = 0.1f;
        rl[row] = ce * w;
    }
}

__global__ void loss_reduce_kernel(const float* __restrict__ rl, float* __restrict__ out)
{
    __shared__ float sm[1024];
    float s = 0.f;
    for (int i = threadIdx.x; i < BT_; i += 1024) s += rl[i];
    sm[threadIdx.x] = s;
    __syncthreads();
    for (int st = 512; st > 0; st >>= 1) {
        if (threadIdx.x < st) sm[threadIdx.x] += sm[threadIdx.x + st];
        __syncthreads();
    }
    if (threadIdx.x == 0) *out = sm[0] * (1.f / BT_);
}

// ---------------------------------------------------------------------------
// Host driver
// ---------------------------------------------------------------------------
static inline void gemm_big(const float* A, int lda, long long sA,
                            const float* Bm, int ldb, long long sB,
                            float* C, int ldc, long long sC,
                            int M, int N, int K, int batch,
                            const float* bias, const float* resid, int ldr, long long sR,
                            int flags, float scale)
{
    dim3 grid(N / 128, M / 128, batch);
    mma_gemm<128, 128, 2, 4><<<grid, 256>>>(A, lda, sA, Bm, ldb, sB, C, ldc, sC,
                                            M, N, K, bias, resid, ldr, sR, flags, scale);
}

static inline void gemm_nar(const float* A, int lda, long long sA,
                            const float* Bm, int ldb, long long sB,
                            float* C, int ldc, long long sC,
                            int M, int N, int K, int batch,
                            const float* bias, const float* resid, int ldr, long long sR,
                            int flags, float scale)
{
    dim3 grid(N / 64, M / 128, batch);
    mma_gemm<128, 64, 4, 2><<<grid, 256>>>(A, lda, sA, Bm, ldb, sB, C, ldc, sC,
                                           M, N, K, bias, resid, ldr, sR, flags, scale);
}

extern "C" void kernel_launch(void* const* d_in, const int* in_sizes, int n_in,
                              void* d_out, int out_size)
{
    const int*   idx = (const int*)d_in[0];
    const int*   tgt = (const int*)d_in[1];
    const float* tok = (const float*)d_in[2];
    const float* pos = (const float*)d_in[3];
    const float* Wq  = (const float*)d_in[4];
    const float* Wk  = (const float*)d_in[5];
    const float* Wv  = (const float*)d_in[6];
    const float* Wp  = (const float*)d_in[7];
    const float* bp  = (const float*)d_in[8];
    const float* W1  = (const float*)d_in[9];
    const float* b1  = (const float*)d_in[10];
    const float* W2  = (const float*)d_in[11];
    const float* b2  = (const float*)d_in[12];
    const float* l1s = (const float*)d_in[13];
    const float* l1b = (const float*)d_in[14];
    const float* l2s = (const float*)d_in[15];
    const float* l2b = (const float*)d_in[16];
    const float* lfs = (const float*)d_in[17];
    const float* lfb = (const float*)d_in[18];
    const float* Wh  = (const float*)d_in[19];
    const float* bh  = (const float*)d_in[20];
    float* out = (float*)d_out;

    float *x, *h, *q, *k, *v, *s, *o, *oc, *ff, *rl;
    cudaGetSymbolAddress((void**)&x,  g_x);
    cudaGetSymbolAddress((void**)&h,  g_h);
    cudaGetSymbolAddress((void**)&q,  g_q);
    cudaGetSymbolAddress((void**)&k,  g_k);
    cudaGetSymbolAddress((void**)&v,  g_v);
    cudaGetSymbolAddress((void**)&s,  g_s);
    cudaGetSymbolAddress((void**)&o,  g_o);
    cudaGetSymbolAddress((void**)&oc, g_oc);
    cudaGetSymbolAddress((void**)&ff, g_ff);
    cudaGetSymbolAddress((void**)&rl, g_rl);

    embed_kernel<<<BT_, 256>>>(idx, tok, pos, x);

    const long long hW  = (long long)E_ * D_;
    const long long qS  = (long long)BT_ * D_;
    const long long aS  = (long long)T_ * D_;
    const long long sS  = (long long)T_ * T_;

    for (int l = 0; l < L_; l++) {
        ln_kernel<<<BT_, 256>>>(x, h, l1s + l * E_, l1b + l * E_);

        // QKV, batched over 16 heads (N=64)
        gemm_nar(h, E_, 0, Wq + (long long)l * H_ * hW, D_, hW, q, D_, qS,
                 BT_, D_, E_, H_, nullptr, nullptr, 0, 0, 0, 0.f);
        gemm_nar(h, E_, 0, Wk + (long long)l * H_ * hW, D_, hW, k, D_, qS,
                 BT_, D_, E_, H_, nullptr, nullptr, 0, 0, 0, 0.f);
        gemm_nar(h, E_, 0, Wv + (long long)l * H_ * hW, D_, hW, v, D_, qS,
                 BT_, D_, E_, H_, nullptr, nullptr, 0, 0, 0, 0.f);

        // Scores = mask(Q @ K^T * E^-0.5), batch 64
        gemm_big(q, D_, aS, k, D_, aS, s, T_, sS,
                 T_, T_, D_, B_ * H_, nullptr, nullptr, 0, 0,
                 FLAG_TRANSB | FLAG_MASK, 0.03125f);

        softmax_kernel<<<B_ * H_ * T_, 256>>>(s);

        // O = P @ V (early exit past causal diagonal)
        gemm_nar(s, T_, sS, v, D_, aS, o, D_, aS,
                 T_, D_, T_, B_ * H_, nullptr, nullptr, 0, 0, FLAG_CAUSAL_A, 0.f);

        merge_heads_kernel<<<(BT_ * E_) / 256, 256>>>(o, oc);

        // x = x + O @ Wproj + bproj
        gemm_big(oc, E_, 0, Wp + (long long)l * E_ * E_, E_, 0, x, E_, 0,
                 BT_, E_, E_, 1, bp + l * E_, x, E_, 0, 0, 0.f);

        ln_kernel<<<BT_, 256>>>(x, h, l2s + l * E_, l2b + l * E_);

        // ff = relu(h @ W1 + b1)
        gemm_big(h, E_, 0, W1 + (long long)l * E_ * FF_, FF_, 0, ff, FF_, 0,
                 BT_, FF_, E_, 1, b1 + l * FF_, nullptr, 0, 0, FLAG_RELU, 0.f);

        // x = x + ff @ W2 + b2
        gemm_big(ff, FF_, 0, W2 + (long long)l * FF_ * E_, E_, 0, x, E_, 0,
                 BT_, E_, FF_, 1, b2 + l * E_, x, E_, 0, 0, 0.f);
    }

    ln_kernel<<<BT_, 256>>>(x, h, lfs, lfb);
    gemm_big(h, E_, 0, Wh, V_, 0, out, V_, 0,
             BT_, V_, E_, 1, bh, nullptr, 0, 0, 0, 0.f);

    loss_rows_kernel<<<BT_, 256>>>(out, tgt, rl);
    if ((long long)out_size >= (long long)BT_ * V_ + 1)
        loss_reduce_kernel<<<1, 1024>>>(rl, out + (long long)BT_ * V_);
}

// round 3
// speedup vs baseline: 4.7087x; 1.0251x over previous
#include <cuda_runtime.h>
#include <math.h>
#include <stdint.h>

// Problem config
#define E_   1024
#define H_   16
#define D_   64
#define L_   6
#define FF_  4096
#define B_   4
#define T_   1024
#define BT_  4096
#define V_   32000

// Scratch
__device__ __align__(16) float g_x[BT_ * E_];
__device__ __align__(16) float g_h[BT_ * E_];
__device__ __align__(16) float g_q[H_ * BT_ * D_];
__device__ __align__(16) float g_k[H_ * BT_ * D_];
__device__ __align__(16) float g_v[H_ * BT_ * D_];
__device__ __align__(16) float g_s[(size_t)B_ * H_ * T_ * T_];
__device__ __align__(16) float g_oc[BT_ * E_];
__device__ __align__(16) float g_ff[BT_ * FF_];
__device__ __align__(16) float g_rl[BT_];

// flags
#define FLAG_MASK     2   // causal mask + scale in epilogue (skip fully-masked tiles)
#define FLAG_RELU     4
#define FLAG_CAUSAL_A 8   // A is causal probs: limit K loop to row0+BM

__device__ __forceinline__ uint32_t f2tf(float f) {
    uint32_t u;
    asm("cvt.rna.tf32.f32 %0, %1;" : "=r"(u) : "f"(f));
    return u;
}

// ---------------------------------------------------------------------------
// tf32 tensor-core GEMM, fragment-major smem (A always, B when TRANSB).
// BK=32. A frag tile (16x8) = 32 lanes x 4 words, stride 132 (pad).
// B frag tile (8x8)  = 32 lanes x 2 words, stride 66 (TRANSB only).
// Non-trans B: [k][n] with stride BN+8 (== 8 mod 32: conflict-free LDS).
// C base = (z/czdiv)*sChi + (z%czdiv)*sClo  (two-level batch stride).
// ---------------------------------------------------------------------------
template<int BM, int BN, int WARPS_M, int WARPS_N, bool TRANSB>
__global__ __launch_bounds__(WARPS_M * WARPS_N * 32, 2)
void mma_gemm(const float* __restrict__ A, int lda, long long sA,
              const float* __restrict__ Bm, int ldb, long long sB,
              float* __restrict__ C, int ldc, long long sChi, long long sClo, int czdiv,
              int M, int N, int K,
              const float* __restrict__ bias,
              const float* __restrict__ resid, int ldr, long long sR,
              int flags, float scale)
{
    constexpr int BK = 32;
    constexpr int NT = WARPS_M * WARPS_N * 32;
    constexpr int WM = BM / WARPS_M;
    constexpr int WN = BN / WARPS_N;
    constexpr int MI = WM / 16;
    constexpr int NI = WN / 8;
    constexpr int TA = 132;                 // A fragment-tile stride (words)
    constexpr int TB = 66;                  // B fragment-tile stride (words)
    constexpr int BSTN = BN + 8;            // non-trans B row stride (words)
    constexpr int A_WORDS = (BM / 16) * 4 * TA;
    constexpr int B_WORDS = TRANSB ? (BN / 8) * 4 * TB : BK * BSTN;
    constexpr int AV = BM * BK / (4 * NT);  // float4 per thread (A)
    constexpr int BV = BN * BK / (4 * NT);  // float4 per thread (B)

    __shared__ uint32_t As[A_WORDS];
    __shared__ uint32_t Bs[B_WORDS];

    const int z = blockIdx.z;
    A  += (long long)z * sA;
    Bm += (long long)z * sB;
    C  += (long long)(z / czdiv) * sChi + (long long)(z % czdiv) * sClo;
    if (resid) resid += (long long)z * sR;

    const int row0 = blockIdx.y * BM;
    const int col0 = blockIdx.x * BN;
    const int tid  = threadIdx.x;
    const int warp = tid >> 5;
    const int lane = tid & 31;
    const int wm   = (warp / WARPS_N) * WM;
    const int wn   = (warp % WARPS_N) * WN;
    const int wm16 = wm >> 4;
    const int wn8  = wn >> 3;
    const int qr   = lane >> 2;
    const int qc   = lane & 3;

    // fully-masked score tile: nothing to compute, nothing read downstream
    if ((flags & FLAG_MASK) && (col0 > row0 + BM - 1)) return;

    int Klim = K;
    if (flags & FLAG_CAUSAL_A) { int lim = row0 + BM; if (lim < Klim) Klim = lim; }

    float acc[MI][NI][4];
#pragma unroll
    for (int i = 0; i < MI; i++)
#pragma unroll
        for (int j = 0; j < NI; j++)
#pragma unroll
            for (int t = 0; t < 4; t++) acc[i][j][t] = 0.f;

    float4 ra[AV], rb[BV];

    // ---- gmem loads (register staging) ----
    auto loadA = [&](int k0) {
#pragma unroll
        for (int i = 0; i < AV; i++) {
            int e = tid + i * NT;
            int m = e >> 3, kq = e & 7;
            ra[i] = *(const float4*)(A + (long long)(row0 + m) * lda + k0 + kq * 4);
        }
    };
    auto loadB = [&](int k0) {
#pragma unroll
        for (int i = 0; i < BV; i++) {
            int e = tid + i * NT;
            if (TRANSB) {
                int n = e >> 3, kq = e & 7;
                rb[i] = *(const float4*)(Bm + (long long)(col0 + n) * ldb + k0 + kq * 4);
            } else {
                int kk = e / (BN / 4), nq = e % (BN / 4);
                rb[i] = *(const float4*)(Bm + (long long)(k0 + kk) * ldb + col0 + nq * 4);
            }
        }
    };

    loadA(0); loadB(0);

    for (int k0 = 0; k0 < Klim; k0 += BK) {
        __syncthreads();
        // ---- store A fragment-major ----
#pragma unroll
        for (int i = 0; i < AV; i++) {
            int e = tid + i * NT;
            int m = e >> 3, kq = e & 7;
            int mt = m >> 4, r = m & 15, kt = kq >> 1;
            int base = (mt * 4 + kt) * TA + (r & 7) * 16 + (r >> 3) + 2 * (kq & 1);
            As[base]      = f2tf(ra[i].x);
            As[base + 4]  = f2tf(ra[i].y);
            As[base + 8]  = f2tf(ra[i].z);
            As[base + 12] = f2tf(ra[i].w);
        }
        // ---- store B ----
#pragma unroll
        for (int i = 0; i < BV; i++) {
            int e = tid + i * NT;
            if (TRANSB) {
                int n = e >> 3, kq = e & 7;
                int base = ((n >> 3) * 4 + (kq >> 1)) * TB + (n & 7) * 8 + (kq & 1);
                Bs[base]     = f2tf(rb[i].x);
                Bs[base + 2] = f2tf(rb[i].y);
                Bs[base + 4] = f2tf(rb[i].z);
                Bs[base + 6] = f2tf(rb[i].w);
            } else {
                int kk = e / (BN / 4), nq = e % (BN / 4);
                uint4 t4;
                t4.x = f2tf(rb[i].x); t4.y = f2tf(rb[i].y);
                t4.z = f2tf(rb[i].z); t4.w = f2tf(rb[i].w);
                *(uint4*)&Bs[kk * BSTN + nq * 4] = t4;
            }
        }
        __syncthreads();

        if (k0 + BK < Klim) { loadA(k0 + BK); loadB(k0 + BK); }

        // ---- compute 4 x k8 ----
#pragma unroll
        for (int kt = 0; kt < 4; kt++) {
            uint4 af[MI];
#pragma unroll
            for (int mi = 0; mi < MI; mi++)
                af[mi] = *(const uint4*)&As[((wm16 + mi) * 4 + kt) * TA + lane * 4];
            uint32_t bf[NI][2];
#pragma unroll
            for (int ni = 0; ni < NI; ni++) {
                if (TRANSB) {
                    uint2 t2 = *(const uint2*)&Bs[((wn8 + ni) * 4 + kt) * TB + lane * 2];
                    bf[ni][0] = t2.x; bf[ni][1] = t2.y;
                } else {
                    int n = wn + ni * 8 + qr;
                    bf[ni][0] = Bs[(kt * 8 + qc) * BSTN + n];
                    bf[ni][1] = Bs[(kt * 8 + qc + 4) * BSTN + n];
                }
            }
#pragma unroll
            for (int mi = 0; mi < MI; mi++)
#pragma unroll
                for (int ni = 0; ni < NI; ni++) {
                    asm volatile(
                        "mma.sync.aligned.m16n8k8.row.col.f32.tf32.tf32.f32 "
                        "{%0,%1,%2,%3}, {%4,%5,%6,%7}, {%8,%9}, {%0,%1,%2,%3};\n"
                        : "+f"(acc[mi][ni][0]), "+f"(acc[mi][ni][1]),
                          "+f"(acc[mi][ni][2]), "+f"(acc[mi][ni][3])
                        : "r"(af[mi].x), "r"(af[mi].y), "r"(af[mi].z), "r"(af[mi].w),
                          "r"(bf[ni][0]), "r"(bf[ni][1]));
                }
        }
    }

    // ---- epilogue ----
#pragma unroll
    for (int mi = 0; mi < MI; mi++) {
#pragma unroll
        for (int ni = 0; ni < NI; ni++) {
#pragma unroll
            for (int t = 0; t < 4; t++) {
                int r = row0 + wm + mi * 16 + qr + ((t >= 2) ? 8 : 0);
                int c = col0 + wn + ni * 8 + qc * 2 + (t & 1);
                float vv = acc[mi][ni][t];
                if (flags & FLAG_MASK) vv = (c <= r) ? vv * scale : -1e30f;
                if (bias)  vv += bias[c];
                if (resid) vv += resid[(long long)r * ldr + c];
                if (flags & FLAG_RELU) vv = fmaxf(vv, 0.f);
                C[(long long)r * ldc + c] = vv;
            }
        }
    }
}

// ---------------------------------------------------------------------------
__global__ void embed_kernel(const int* __restrict__ idx,
                             const float* __restrict__ tok,
                             const float* __restrict__ pos,
                             float* __restrict__ x)
{
    int row = blockIdx.x;
    int t   = row & (T_ - 1);
    int tk  = idx[row];
    const float* te = tok + (long long)tk * E_;
    const float* pe = pos + (long long)t  * E_;
    float* xr = x + (long long)row * E_;
    for (int c = threadIdx.x; c < E_; c += blockDim.x)
        xr[c] = te[c] + pe[c];
}

__global__ void ln_kernel(const float* __restrict__ x, float* __restrict__ y,
                          const float* __restrict__ sc, const float* __restrict__ bi)
{
    int row = blockIdx.x;
    const float* xr = x + (long long)row * E_;
    float* yr = y + (long long)row * E_;
    float v[4];
    float sum = 0.f, sq = 0.f;
#pragma unroll
    for (int i = 0; i < 4; i++) {
        v[i] = xr[threadIdx.x + i * 256];
        sum += v[i]; sq += v[i] * v[i];
    }
    __shared__ float s1[256], s2[256];
    s1[threadIdx.x] = sum; s2[threadIdx.x] = sq;
    __syncthreads();
    for (int st = 128; st > 0; st >>= 1) {
        if (threadIdx.x < st) {
            s1[threadIdx.x] += s1[threadIdx.x + st];
            s2[threadIdx.x] += s2[threadIdx.x + st];
        }
        __syncthreads();
    }
    float mean = s1[0] * (1.f / E_);
    float var  = s2[0] * (1.f / E_) - mean * mean;
    float inv  = rsqrtf(var + 1e-5f);
#pragma unroll
    for (int i = 0; i < 4; i++) {
        int c = threadIdx.x + i * 256;
        yr[c] = (v[i] - mean) * inv * sc[c] + bi[c];
    }
}

// Softmax limited to causal extent: row r only needs cols < ru = tile-ceil(r+1)
__global__ void softmax_kernel(float* __restrict__ s)
{
    long long row = blockIdx.x;
    int r  = (int)(row & (T_ - 1));
    int ru = (((r >> 7) + 1) << 7);
    float* p = s + row * T_;
    int tid = threadIdx.x;
    float m = -1e30f;
    for (int c = tid; c < ru; c += 256) m = fmaxf(m, p[c]);
    __shared__ float sm[256];
    sm[tid] = m; __syncthreads();
    for (int st = 128; st > 0; st >>= 1) {
        if (tid < st) sm[tid] = fmaxf(sm[tid], sm[tid + st]);
        __syncthreads();
    }
    m = sm[0];
    __syncthreads();
    float sum = 0.f;
    for (int c = tid; c < ru; c += 256) sum += __expf(p[c] - m);
    sm[tid] = sum; __syncthreads();
    for (int st = 128; st > 0; st >>= 1) {
        if (tid < st) sm[tid] += sm[tid + st];
        __syncthreads();
    }
    float inv = 1.f / sm[0];
    for (int c = tid; c < ru; c += 256) p[c] = __expf(p[c] - m) * inv;
}

// Two-pass weighted CE per row (1 MUFU/elem instead of 2)
__global__ void loss_rows_kernel(const float* __restrict__ logits,
                                 const int* __restrict__ tgt,
                                 float* __restrict__ rl)
{
    int row = blockIdx.x;
    const float4* lg4 = (const float4*)(logits + (long long)row * V_);
    int tid = threadIdx.x;
    float m = -1e30f;
    for (int c = tid; c < V_ / 4; c += 256) {
        float4 f = lg4[c];
        m = fmaxf(m, fmaxf(fmaxf(f.x, f.y), fmaxf(f.z, f.w)));
    }
    __shared__ float sm[256];
    sm[tid] = m; __syncthreads();
    for (int st = 128; st > 0; st >>= 1) {
        if (tid < st) sm[tid] = fmaxf(sm[tid], sm[tid + st]);
        __syncthreads();
    }
    m = sm[0];
    __syncthreads();
    float s = 0.f;
    for (int c = tid; c < V_ / 4; c += 256) {
        float4 f = lg4[c];
        s += __expf(f.x - m) + __expf(f.y - m) + __expf(f.z - m) + __expf(f.w - m);
    }
    sm[tid] = s; __syncthreads();
    for (int st = 128; st > 0; st >>= 1) {
        if (tid < st) sm[tid] += sm[tid + st];
        __syncthreads();
    }
    if (tid == 0) {
        const float* lg = logits + (long long)row * V_;
        float lse = m + __logf(sm[0]);
        int t = tgt[row];
        float ce = lse - lg[t];
        float w = 1.f;
        if (t == 4 || t == 3 || t == 1) w = 1.5f;
        if (t == 2) w = 2.0f;
        if (t == 0) w = 0.1f;
        rl[row] = ce * w;
    }
}

__global__ void loss_reduce_kernel(const float* __restrict__ rl, float* __restrict__ out)
{
    __shared__ float sm[1024];
    float s = 0.f;
    for (int i = threadIdx.x; i < BT_; i += 1024) s += rl[i];
    sm[threadIdx.x] = s;
    __syncthreads();
    for (int st = 512; st > 0; st >>= 1) {
        if (threadIdx.x < st) sm[threadIdx.x] += sm[threadIdx.x + st];
        __syncthreads();
    }
    if (threadIdx.x == 0) *out = sm[0] * (1.f / BT_);
}

// ---------------------------------------------------------------------------
// Host-side launch helpers
// ---------------------------------------------------------------------------
static inline void gemm128(const float* A, int lda, long long sA,
                           const float* Bm, int ldb, long long sB,
                           float* C, int ldc, long long sC,
                           int M, int N, int K, int batch,
                           const float* bias, const float* resid, int ldr, long long sR,
                           int flags, float scale)
{
    dim3 grid(N / 128, M / 128, batch);
    mma_gemm<128, 128, 2, 4, false><<<grid, 256>>>(A, lda, sA, Bm, ldb, sB,
        C, ldc, sC, 0, 1, M, N, K, bias, resid, ldr, sR, flags, scale);
}

static inline void gemm128t(const float* A, int lda, long long sA,
                            const float* Bm, int ldb, long long sB,
                            float* C, int ldc, long long sC,
                            int M, int N, int K, int batch,
                            int flags, float scale)
{
    dim3 grid(N / 128, M / 128, batch);
    mma_gemm<128, 128, 2, 4, true><<<grid, 256>>>(A, lda, sA, Bm, ldb, sB,
        C, ldc, sC, 0, 1, M, N, K, nullptr, nullptr, 0, 0, flags, scale);
}

static inline void gemm64(const float* A, int lda, long long sA,
                          const float* Bm, int ldb, long long sB,
                          float* C, int ldc, long long sChi, long long sClo, int czdiv,
                          int M, int N, int K, int batch, int flags)
{
    dim3 grid(N / 64, M / 128, batch);
    mma_gemm<128, 64, 2, 4, false><<<grid, 256>>>(A, lda, sA, Bm, ldb, sB,
        C, ldc, sChi, sClo, czdiv, M, N, K, nullptr, nullptr, 0, 0, flags, 0.f);
}

extern "C" void kernel_launch(void* const* d_in, const int* in_sizes, int n_in,
                              void* d_out, int out_size)
{
    const int*   idx = (const int*)d_in[0];
    const int*   tgt = (const int*)d_in[1];
    const float* tok = (const float*)d_in[2];
    const float* pos = (const float*)d_in[3];
    const float* Wq  = (const float*)d_in[4];
    const float* Wk  = (const float*)d_in[5];
    const float* Wv  = (const float*)d_in[6];
    const float* Wp  = (const float*)d_in[7];
    const float* bp  = (const float*)d_in[8];
    const float* W1  = (const float*)d_in[9];
    const float* b1  = (const float*)d_in[10];
    const float* W2  = (const float*)d_in[11];
    const float* b2  = (const float*)d_in[12];
    const float* l1s = (const float*)d_in[13];
    const float* l1b = (const float*)d_in[14];
    const float* l2s = (const float*)d_in[15];
    const float* l2b = (const float*)d_in[16];
    const float* lfs = (const float*)d_in[17];
    const float* lfb = (const float*)d_in[18];
    const float* Wh  = (const float*)d_in[19];
    const float* bh  = (const float*)d_in[20];
    float* out = (float*)d_out;

    float *x, *h, *q, *k, *v, *s, *oc, *ff, *rl;
    cudaGetSymbolAddress((void**)&x,  g_x);
    cudaGetSymbolAddress((void**)&h,  g_h);
    cudaGetSymbolAddress((void**)&q,  g_q);
    cudaGetSymbolAddress((void**)&k,  g_k);
    cudaGetSymbolAddress((void**)&v,  g_v);
    cudaGetSymbolAddress((void**)&s,  g_s);
    cudaGetSymbolAddress((void**)&oc, g_oc);
    cudaGetSymbolAddress((void**)&ff, g_ff);
    cudaGetSymbolAddress((void**)&rl, g_rl);

    embed_kernel<<<BT_, 256>>>(idx, tok, pos, x);

    const long long hW = (long long)E_ * D_;
    const long long qS = (long long)BT_ * D_;
    const long long aS = (long long)T_ * D_;
    const long long sS = (long long)T_ * T_;

    for (int l = 0; l < L_; l++) {
        ln_kernel<<<BT_, 256>>>(x, h, l1s + l * E_, l1b + l * E_);

        // QKV, batched over heads: q/k/v layout [h][b*T+t][d]
        gemm64(h, E_, 0, Wq + (long long)l * H_ * hW, D_, hW, q, D_, qS, 0, 1,
               BT_, D_, E_, H_, 0);
        gemm64(h, E_, 0, Wk + (long long)l * H_ * hW, D_, hW, k, D_, qS, 0, 1,
               BT_, D_, E_, H_, 0);
        gemm64(h, E_, 0, Wv + (long long)l * H_ * hW, D_, hW, v, D_, qS, 0, 1,
               BT_, D_, E_, H_, 0);

        // Scores = mask(Q @ K^T * E^-0.5), batch z = h*B+b
        gemm128t(q, D_, aS, k, D_, aS, s, T_, sS,
                 T_, T_, D_, B_ * H_, FLAG_MASK, 0.03125f);

        softmax_kernel<<<B_ * H_ * T_, 256>>>(s);

        // O = P @ V, written directly into concat layout oc[b*T+t][h*D+d]
        // z = h*B+b:  C += (z/B)*D + (z%B)*(T*E)
        gemm64(s, T_, sS, v, D_, aS, oc + 0, E_, D_, (long long)T_ * E_, B_,
               T_, D_, T_, B_ * H_, FLAG_CAUSAL_A);

        // x = x + O @ Wproj + bproj
        gemm128(oc, E_, 0, Wp + (long long)l * E_ * E_, E_, 0, x, E_, 0,
                BT_, E_, E_, 1, bp + l * E_, x, E_, 0, 0, 0.f);

        ln_kernel<<<BT_, 256>>>(x, h, l2s + l * E_, l2b + l * E_);

        // ff = relu(h @ W1 + b1)
        gemm128(h, E_, 0, W1 + (long long)l * E_ * FF_, FF_, 0, ff, FF_, 0,
                BT_, FF_, E_, 1, b1 + l * FF_, nullptr, 0, 0, FLAG_RELU, 0.f);

        // x = x + ff @ W2 + b2
        gemm128(ff, FF_, 0, W2 + (long long)l * FF_ * E_, E_, 0, x, E_, 0,
                BT_, E_, FF_, 1, b2 + l * E_, x, E_, 0, 0, 0.f);
    }

    ln_kernel<<<BT_, 256>>>(x, h, lfs, lfb);
    gemm128(h, E_, 0, Wh, V_, 0, out, V_, 0,
            BT_, V_, E_, 1, bh, nullptr, 0, 0, 0, 0.f);

    loss_rows_kernel<<<BT_, 256>>>(out, tgt, rl);
    if ((long long)out_size >= (long long)BT_ * V_ + 1)
        loss_reduce_kernel<<<1, 1024>>>(rl, out + (long long)BT_ * V_);
}

// round 4
// speedup vs baseline: 5.4371x; 1.1547x over previous
#include <cuda_runtime.h>
#include <math.h>
#include <stdint.h>

// Problem config
#define E_   1024
#define H_   16
#define D_   64
#define L_   6
#define FF_  4096
#define B_   4
#define T_   1024
#define BT_  4096
#define V_   32000

// Activation scratch
__device__ __align__(16) float g_x[BT_ * E_];
__device__ __align__(16) float g_h[BT_ * E_];
__device__ __align__(16) float g_q[H_ * BT_ * D_];
__device__ __align__(16) float g_k[H_ * BT_ * D_];
__device__ __align__(16) float g_v[H_ * BT_ * D_];
__device__ __align__(16) float g_s[(size_t)B_ * H_ * T_ * T_];
__device__ __align__(16) float g_oc[BT_ * E_];
__device__ __align__(16) float g_ff[BT_ * FF_];
__device__ __align__(16) float g_rl[BT_];

// tf32-rounded weight copies
__device__ __align__(16) float g_wq[L_ * H_ * E_ * D_];
__device__ __align__(16) float g_wk[L_ * H_ * E_ * D_];
__device__ __align__(16) float g_wv[L_ * H_ * E_ * D_];
__device__ __align__(16) float g_wp[L_ * E_ * E_];
__device__ __align__(16) float g_w1[(size_t)L_ * E_ * FF_];
__device__ __align__(16) float g_w2[(size_t)L_ * FF_ * E_];
__device__ __align__(16) float g_wh[(size_t)E_ * V_];

// flags
#define FLAG_MASK     2
#define FLAG_RELU     4
#define FLAG_CAUSAL_A 8
#define FLAG_ROUND    16   // round output to tf32 (it feeds another GEMM)

__device__ __forceinline__ uint32_t f2tf(float f) {
    uint32_t u;
    asm("cvt.rna.tf32.f32 %0, %1;" : "=r"(u) : "f"(f));
    return u;
}
__device__ __forceinline__ float tfround(float f) { return __uint_as_float(f2tf(f)); }

__device__ __forceinline__ void cpa16(void* s, const void* g) {
    uint32_t sa = (uint32_t)__cvta_generic_to_shared(s);
    asm volatile("cp.async.cg.shared.global [%0], [%1], 16;\n" :: "r"(sa), "l"(g));
}
__device__ __forceinline__ void cpa_commit() { asm volatile("cp.async.commit_group;\n"); }
__device__ __forceinline__ void cpa_wait1()  { asm volatile("cp.async.wait_group 1;\n"); }
__device__ __forceinline__ void cpa_wait0()  { asm volatile("cp.async.wait_group 0;\n"); }

// ---------------------------------------------------------------------------
// tf32 GEMM v2: inputs already tf32-rounded in gmem. cp.async double-buffered.
// A smem [m][k] stride 36; B smem: TRANSB -> [n][k] stride 36, else [k][n]
// stride BN+8. All frag LDS bank-conflict-free. BK=32, 8 warps (2x4).
// ---------------------------------------------------------------------------
template<int BM, int BN, bool TRANSB>
__global__ __launch_bounds__(256, 2)
void mma_gemm(const float* __restrict__ A, int lda, long long sA,
              const float* __restrict__ Bm, int ldb, long long sB,
              float* __restrict__ C, int ldc, long long sChi, long long sClo, int czdiv,
              int M, int N, int K,
              const float* __restrict__ bias,
              const float* __restrict__ resid, int ldr, long long sR,
              int flags, float scale)
{
    constexpr int BK  = 32;
    constexpr int WM  = BM / 2;           // 2 warp rows
    constexpr int WN  = BN / 4;           // 4 warp cols
    constexpr int MI  = WM / 16;
    constexpr int NI  = WN / 8;
    constexpr int AST = 36;
    constexpr int BSTN = BN + 8;
    constexpr int ASZ = BM * AST;
    constexpr int BSZ = TRANSB ? BN * 36 : BK * BSTN;
    constexpr int AV  = BM * BK / (4 * 256);
    constexpr int BV  = BN * BK / (4 * 256);

    extern __shared__ __align__(16) float dsm[];
    float* Abuf = dsm;                 // 2 * ASZ
    float* Bbuf = dsm + 2 * ASZ;       // 2 * BSZ

    const int z = blockIdx.z;
    A  += (long long)z * sA;
    Bm += (long long)z * sB;
    C  += (long long)(z / czdiv) * sChi + (long long)(z % czdiv) * sClo;
    if (resid) resid += (long long)z * sR;

    const int row0 = blockIdx.y * BM;
    const int col0 = blockIdx.x * BN;

    if ((flags & FLAG_MASK) && (col0 > row0 + BM - 1)) return;

    const int tid  = threadIdx.x;
    const int warp = tid >> 5;
    const int lane = tid & 31;
    const int wm   = (warp >> 2) * WM;
    const int wn   = (warp & 3) * WN;
    const int qr   = lane >> 2;
    const int qc   = lane & 3;

    int Klim = K;
    if (flags & FLAG_CAUSAL_A) { int lim = row0 + BM; if (lim < Klim) Klim = lim; }
    const int nk = Klim / BK;

    float acc[MI][NI][4];
#pragma unroll
    for (int i = 0; i < MI; i++)
#pragma unroll
        for (int j = 0; j < NI; j++)
#pragma unroll
            for (int t = 0; t < 4; t++) acc[i][j][t] = 0.f;

    auto issue = [&](int k0, int buf) {
        float* as = Abuf + buf * ASZ;
#pragma unroll
        for (int i = 0; i < AV; i++) {
            int e = tid + i * 256;
            int m = e >> 3, kq = e & 7;
            cpa16(&as[m * AST + kq * 4], A + (long long)(row0 + m) * lda + k0 + kq * 4);
        }
        float* bs = Bbuf + buf * BSZ;
#pragma unroll
        for (int i = 0; i < BV; i++) {
            int e = tid + i * 256;
            if (TRANSB) {
                int n = e >> 3, kq = e & 7;
                cpa16(&bs[n * 36 + kq * 4], Bm + (long long)(col0 + n) * ldb + k0 + kq * 4);
            } else {
                int kk = e / (BN / 4), nq = e % (BN / 4);
                cpa16(&bs[kk * BSTN + nq * 4], Bm + (long long)(k0 + kk) * ldb + col0 + nq * 4);
            }
        }
        cpa_commit();
    };

    issue(0, 0);
    for (int it = 0; it < nk; it++) {
        if (it + 1 < nk) { issue((it + 1) * BK, (it + 1) & 1); cpa_wait1(); }
        else             { cpa_wait0(); }
        __syncthreads();

        const uint32_t* as = (const uint32_t*)(Abuf + (it & 1) * ASZ);
        const uint32_t* bs = (const uint32_t*)(Bbuf + (it & 1) * BSZ);

#pragma unroll
        for (int kt = 0; kt < 4; kt++) {
            const int kk = kt * 8;
            uint32_t a[MI][4];
#pragma unroll
            for (int mi = 0; mi < MI; mi++) {
                int r = wm + mi * 16 + qr;
                a[mi][0] = as[r * AST + kk + qc];
                a[mi][1] = as[(r + 8) * AST + kk + qc];
                a[mi][2] = as[r * AST + kk + qc + 4];
                a[mi][3] = as[(r + 8) * AST + kk + qc + 4];
            }
            uint32_t b[NI][2];
#pragma unroll
            for (int ni = 0; ni < NI; ni++) {
                int n = wn + ni * 8 + qr;
                if (TRANSB) {
                    b[ni][0] = bs[n * 36 + kk + qc];
                    b[ni][1] = bs[n * 36 + kk + qc + 4];
                } else {
                    b[ni][0] = bs[(kk + qc) * BSTN + n];
                    b[ni][1] = bs[(kk + qc + 4) * BSTN + n];
                }
            }
#pragma unroll
            for (int mi = 0; mi < MI; mi++)
#pragma unroll
                for (int ni = 0; ni < NI; ni++) {
                    asm volatile(
                        "mma.sync.aligned.m16n8k8.row.col.f32.tf32.tf32.f32 "
                        "{%0,%1,%2,%3}, {%4,%5,%6,%7}, {%8,%9}, {%0,%1,%2,%3};\n"
                        : "+f"(acc[mi][ni][0]), "+f"(acc[mi][ni][1]),
                          "+f"(acc[mi][ni][2]), "+f"(acc[mi][ni][3])
                        : "r"(a[mi][0]), "r"(a[mi][1]), "r"(a[mi][2]), "r"(a[mi][3]),
                          "r"(b[ni][0]), "r"(b[ni][1]));
                }
        }
        __syncthreads();
    }

    // epilogue: float2 stores
#pragma unroll
    for (int mi = 0; mi < MI; mi++) {
#pragma unroll
        for (int ni = 0; ni < NI; ni++) {
#pragma unroll
            for (int half = 0; half < 2; half++) {
                int r = row0 + wm + mi * 16 + qr + half * 8;
                int c = col0 + wn + ni * 8 + qc * 2;
                float v0 = acc[mi][ni][half * 2];
                float v1 = acc[mi][ni][half * 2 + 1];
                if (flags & FLAG_MASK) {
                    v0 = (c     <= r) ? v0 * scale : -1e30f;
                    v1 = (c + 1 <= r) ? v1 * scale : -1e30f;
                }
                if (bias) { v0 += bias[c]; v1 += bias[c + 1]; }
                if (resid) {
                    float2 rr = *(const float2*)(resid + (long long)r * ldr + c);
                    v0 += rr.x; v1 += rr.y;
                }
                if (flags & FLAG_RELU) { v0 = fmaxf(v0, 0.f); v1 = fmaxf(v1, 0.f); }
                if (flags & FLAG_ROUND) { v0 = tfround(v0); v1 = tfround(v1); }
                *(float2*)(C + (long long)r * ldc + c) = make_float2(v0, v1);
            }
        }
    }
}

// ---------------------------------------------------------------------------
__global__ void tf32_cvt_kernel(const float4* __restrict__ in, float4* __restrict__ out, int n4)
{
    int i = blockIdx.x * 256 + threadIdx.x;
    int stride = gridDim.x * 256;
    for (; i < n4; i += stride) {
        float4 f = in[i];
        f.x = tfround(f.x); f.y = tfround(f.y);
        f.z = tfround(f.z); f.w = tfround(f.w);
        out[i] = f;
    }
}

__global__ void embed_kernel(const int* __restrict__ idx,
                             const float* __restrict__ tok,
                             const float* __restrict__ pos,
                             float* __restrict__ x)
{
    int row = blockIdx.x;
    int t   = row & (T_ - 1);
    int tk  = idx[row];
    const float* te = tok + (long long)tk * E_;
    const float* pe = pos + (long long)t  * E_;
    float* xr = x + (long long)row * E_;
    for (int c = threadIdx.x; c < E_; c += blockDim.x)
        xr[c] = te[c] + pe[c];
}

// LN with tf32-rounded output (output always feeds a GEMM A operand)
__global__ void ln_kernel(const float* __restrict__ x, float* __restrict__ y,
                          const float* __restrict__ sc, const float* __restrict__ bi)
{
    int row = blockIdx.x;
    const float* xr = x + (long long)row * E_;
    float* yr = y + (long long)row * E_;
    float v[4];
    float sum = 0.f, sq = 0.f;
#pragma unroll
    for (int i = 0; i < 4; i++) {
        v[i] = xr[threadIdx.x + i * 256];
        sum += v[i]; sq += v[i] * v[i];
    }
    __shared__ float s1[256], s2[256];
    s1[threadIdx.x] = sum; s2[threadIdx.x] = sq;
    __syncthreads();
    for (int st = 128; st > 0; st >>= 1) {
        if (threadIdx.x < st) {
            s1[threadIdx.x] += s1[threadIdx.x + st];
            s2[threadIdx.x] += s2[threadIdx.x + st];
        }
        __syncthreads();
    }
    float mean = s1[0] * (1.f / E_);
    float var  = s2[0] * (1.f / E_) - mean * mean;
    float inv  = rsqrtf(var + 1e-5f);
#pragma unroll
    for (int i = 0; i < 4; i++) {
        int c = threadIdx.x + i * 256;
        yr[c] = tfround((v[i] - mean) * inv * sc[c] + bi[c]);
    }
}

// Final LN: NOT rounded (feeds head GEMM... actually also a GEMM input; keep
// rounded path separate) -- head GEMM A must be tf32 too, so round as well.
__global__ void softmax_kernel(float* __restrict__ s)
{
    long long row = blockIdx.x;
    int r  = (int)(row & (T_ - 1));
    int ru = (((r >> 7) + 1) << 7);
    float* p = s + row * T_;
    int tid = threadIdx.x;
    float m = -1e30f;
    for (int c = tid; c < ru; c += 256) m = fmaxf(m, p[c]);
    __shared__ float sm[256];
    sm[tid] = m; __syncthreads();
    for (int st = 128; st > 0; st >>= 1) {
        if (tid < st) sm[tid] = fmaxf(sm[tid], sm[tid + st]);
        __syncthreads();
    }
    m = sm[0];
    __syncthreads();
    float sum = 0.f;
    for (int c = tid; c < ru; c += 256) sum += __expf(p[c] - m);
    sm[tid] = sum; __syncthreads();
    for (int st = 128; st > 0; st >>= 1) {
        if (tid < st) sm[tid] += sm[tid + st];
        __syncthreads();
    }
    float inv = 1.f / sm[0];
    for (int c = tid; c < ru; c += 256) p[c] = tfround(__expf(p[c] - m) * inv);
}

__global__ void loss_rows_kernel(const float* __restrict__ logits,
                                 const int* __restrict__ tgt,
                                 float* __restrict__ rl)
{
    int row = blockIdx.x;
    const float4* lg4 = (const float4*)(logits + (long long)row * V_);
    int tid = threadIdx.x;
    float m = -1e30f;
    for (int c = tid; c < V_ / 4; c += 256) {
        float4 f = lg4[c];
        m = fmaxf(m, fmaxf(fmaxf(f.x, f.y), fmaxf(f.z, f.w)));
    }
    __shared__ float sm[256];
    sm[tid] = m; __syncthreads();
    for (int st = 128; st > 0; st >>= 1) {
        if (tid < st) sm[tid] = fmaxf(sm[tid], sm[tid + st]);
        __syncthreads();
    }
    m = sm[0];
    __syncthreads();
    float s = 0.f;
    for (int c = tid; c < V_ / 4; c += 256) {
        float4 f = lg4[c];
        s += __expf(f.x - m) + __expf(f.y - m) + __expf(f.z - m) + __expf(f.w - m);
    }
    sm[tid] = s; __syncthreads();
    for (int st = 128; st > 0; st >>= 1) {
        if (tid < st) sm[tid] += sm[tid + st];
        __syncthreads();
    }
    if (tid == 0) {
        const float* lg = logits + (long long)row * V_;
        float lse = m + __logf(sm[0]);
        int t = tgt[row];
        float ce = lse - lg[t];
        float w = 1.f;
        if (t == 4 || t == 3 || t == 1) w = 1.5f;
        if (t == 2) w = 2.0f;
        if (t == 0) w = 0.1f;
        rl[row] = ce * w;
    }
}

__global__ void loss_reduce_kernel(const float* __restrict__ rl, float* __restrict__ out)
{
    __shared__ float sm[1024];
    float s = 0.f;
    for (int i = threadIdx.x; i < BT_; i += 1024) s += rl[i];
    sm[threadIdx.x] = s;
    __syncthreads();
    for (int st = 512; st > 0; st >>= 1) {
        if (threadIdx.x < st) sm[threadIdx.x] += sm[threadIdx.x + st];
        __syncthreads();
    }
    if (threadIdx.x == 0) *out = sm[0] * (1.f / BT_);
}

// ---------------------------------------------------------------------------
// Host helpers
// ---------------------------------------------------------------------------
#define SMEM_G128  (2 * 128 * 36 + 2 * 32 * 136) * 4   // 71680
#define SMEM_G128T (2 * 128 * 36 + 2 * 128 * 36) * 4   // 73728
#define SMEM_G64   (2 * 128 * 36 + 2 * 32 * 72) * 4    // 55296

static inline void gemm128(const float* A, int lda, long long sA,
                           const float* Bm, int ldb, long long sB,
                           float* C, int ldc, long long sC,
                           int M, int N, int K, int batch,
                           const float* bias, const float* resid, int ldr, long long sR,
                           int flags, float scale)
{
    dim3 grid(N / 128, M / 128, batch);
    mma_gemm<128, 128, false><<<grid, 256, SMEM_G128>>>(A, lda, sA, Bm, ldb, sB,
        C, ldc, sC, 0, 1, M, N, K, bias, resid, ldr, sR, flags, scale);
}

static inline void gemm128t(const float* A, int lda, long long sA,
                            const float* Bm, int ldb, long long sB,
                            float* C, int ldc, long long sC,
                            int M, int N, int K, int batch,
                            int flags, float scale)
{
    dim3 grid(N / 128, M / 128, batch);
    mma_gemm<128, 128, true><<<grid, 256, SMEM_G128T>>>(A, lda, sA, Bm, ldb, sB,
        C, ldc, sC, 0, 1, M, N, K, nullptr, nullptr, 0, 0, flags, scale);
}

static inline void gemm64(const float* A, int lda, long long sA,
                          const float* Bm, int ldb, long long sB,
                          float* C, int ldc, long long sChi, long long sClo, int czdiv,
                          int M, int N, int K, int batch, int flags)
{
    dim3 grid(N / 64, M / 128, batch);
    mma_gemm<128, 64, false><<<grid, 256, SMEM_G64>>>(A, lda, sA, Bm, ldb, sB,
        C, ldc, sChi, sClo, czdiv, M, N, K, nullptr, nullptr, 0, 0, flags, 0.f);
}

extern "C" void kernel_launch(void* const* d_in, const int* in_sizes, int n_in,
                              void* d_out, int out_size)
{
    const int*   idx = (const int*)d_in[0];
    const int*   tgt = (const int*)d_in[1];
    const float* tok = (const float*)d_in[2];
    const float* pos = (const float*)d_in[3];
    const float* Wq  = (const float*)d_in[4];
    const float* Wk  = (const float*)d_in[5];
    const float* Wv  = (const float*)d_in[6];
    const float* Wp  = (const float*)d_in[7];
    const float* bp  = (const float*)d_in[8];
    const float* W1  = (const float*)d_in[9];
    const float* b1  = (const float*)d_in[10];
    const float* W2  = (const float*)d_in[11];
    const float* b2  = (const float*)d_in[12];
    const float* l1s = (const float*)d_in[13];
    const float* l1b = (const float*)d_in[14];
    const float* l2s = (const float*)d_in[15];
    const float* l2b = (const float*)d_in[16];
    const float* lfs = (const float*)d_in[17];
    const float* lfb = (const float*)d_in[18];
    const float* Wh  = (const float*)d_in[19];
    const float* bh  = (const float*)d_in[20];
    float* out = (float*)d_out;

    static int attr_done = 0;
    // idempotent; cheap. Allowed host API (not an allocation).
    cudaFuncSetAttribute(mma_gemm<128, 128, false>,
                         cudaFuncAttributeMaxDynamicSharedMemorySize, SMEM_G128);
    cudaFuncSetAttribute(mma_gemm<128, 128, true>,
                         cudaFuncAttributeMaxDynamicSharedMemorySize, SMEM_G128T);
    cudaFuncSetAttribute(mma_gemm<128, 64, false>,
                         cudaFuncAttributeMaxDynamicSharedMemorySize, SMEM_G64);
    (void)attr_done;

    float *x, *h, *q, *k, *v, *s, *oc, *ff, *rl;
    float *wq, *wk, *wv, *wp, *w1, *w2, *wh;
    cudaGetSymbolAddress((void**)&x,  g_x);
    cudaGetSymbolAddress((void**)&h,  g_h);
    cudaGetSymbolAddress((void**)&q,  g_q);
    cudaGetSymbolAddress((void**)&k,  g_k);
    cudaGetSymbolAddress((void**)&v,  g_v);
    cudaGetSymbolAddress((void**)&s,  g_s);
    cudaGetSymbolAddress((void**)&oc, g_oc);
    cudaGetSymbolAddress((void**)&ff, g_ff);
    cudaGetSymbolAddress((void**)&rl, g_rl);
    cudaGetSymbolAddress((void**)&wq, g_wq);
    cudaGetSymbolAddress((void**)&wk, g_wk);
    cudaGetSymbolAddress((void**)&wv, g_wv);
    cudaGetSymbolAddress((void**)&wp, g_wp);
    cudaGetSymbolAddress((void**)&w1, g_w1);
    cudaGetSymbolAddress((void**)&w2, g_w2);
    cudaGetSymbolAddress((void**)&wh, g_wh);

    // Convert weights to tf32 (once per launch; ~150us total)
    {
        const int TPB = 256, GR = 2048;
        tf32_cvt_kernel<<<GR, TPB>>>((const float4*)Wq, (float4*)wq, L_ * H_ * E_ * D_ / 4);
        tf32_cvt_kernel<<<GR, TPB>>>((const float4*)Wk, (float4*)wk, L_ * H_ * E_ * D_ / 4);
        tf32_cvt_kernel<<<GR, TPB>>>((const float4*)Wv, (float4*)wv, L_ * H_ * E_ * D_ / 4);
        tf32_cvt_kernel<<<GR, TPB>>>((const float4*)Wp, (float4*)wp, L_ * E_ * E_ / 4);
        tf32_cvt_kernel<<<GR, TPB>>>((const float4*)W1, (float4*)w1, L_ * E_ * FF_ / 4);
        tf32_cvt_kernel<<<GR, TPB>>>((const float4*)W2, (float4*)w2, L_ * FF_ * E_ / 4);
        tf32_cvt_kernel<<<GR, TPB>>>((const float4*)Wh, (float4*)wh, E_ * V_ / 4);
    }

    embed_kernel<<<BT_, 256>>>(idx, tok, pos, x);

    const long long hW = (long long)E_ * D_;
    const long long qS = (long long)BT_ * D_;
    const long long aS = (long long)T_ * D_;
    const long long sS = (long long)T_ * T_;

    for (int l = 0; l < L_; l++) {
        ln_kernel<<<BT_, 256>>>(x, h, l1s + l * E_, l1b + l * E_);

        gemm64(h, E_, 0, wq + (long long)l * H_ * hW, D_, hW, q, D_, qS, 0, 1,
               BT_, D_, E_, H_, FLAG_ROUND);
        gemm64(h, E_, 0, wk + (long long)l * H_ * hW, D_, hW, k, D_, qS, 0, 1,
               BT_, D_, E_, H_, FLAG_ROUND);
        gemm64(h, E_, 0, wv + (long long)l * H_ * hW, D_, hW, v, D_, qS, 0, 1,
               BT_, D_, E_, H_, FLAG_ROUND);

        // Scores = mask(Q @ K^T * E^-0.5)
        gemm128t(q, D_, aS, k, D_, aS, s, T_, sS,
                 T_, T_, D_, B_ * H_, FLAG_MASK, 0.03125f);

        softmax_kernel<<<B_ * H_ * T_, 256>>>(s);

        // O = P @ V -> concat layout oc[b*T+t][h*D+d]; z = h*B+b
        gemm64(s, T_, sS, v, D_, aS, oc, E_, D_, (long long)T_ * E_, B_,
               T_, D_, T_, B_ * H_, FLAG_CAUSAL_A | FLAG_ROUND);

        // x = x + oc @ Wproj + bproj
        gemm128(oc, E_, 0, wp + (long long)l * E_ * E_, E_, 0, x, E_, 0,
                BT_, E_, E_, 1, bp + l * E_, x, E_, 0, 0, 0.f);

        ln_kernel<<<BT_, 256>>>(x, h, l2s + l * E_, l2b + l * E_);

        gemm128(h, E_, 0, w1 + (long long)l * E_ * FF_, FF_, 0, ff, FF_, 0,
                BT_, FF_, E_, 1, b1 + l * FF_, nullptr, 0, 0,
                FLAG_RELU | FLAG_ROUND, 0.f);

        gemm128(ff, FF_, 0, w2 + (long long)l * FF_ * E_, E_, 0, x, E_, 0,
                BT_, E_, FF_, 1, b2 + l * E_, x, E_, 0, 0, 0.f);
    }

    ln_kernel<<<BT_, 256>>>(x, h, lfs, lfb);
    // head: N=32000 = 250 * 128
    gemm128(h, E_, 0, wh, V_, 0, out, V_, 0,
            BT_, V_, E_, 1, bh, nullptr, 0, 0, 0, 0.f);

    loss_rows_kernel<<<BT_, 256>>>(out, tgt, rl);
    if ((long long)out_size >= (long long)BT_ * V_ + 1)
        loss_reduce_kernel<<<1, 1024>>>(rl, out + (long long)BT_ * V_);
}

// round 7
// speedup vs baseline: 6.4807x; 1.1919x over previous
#include <cuda_runtime.h>
#include <math.h>
#include <stdint.h>

// Problem config
#define E_   1024
#define H_   16
#define D_   64
#define L_   6
#define FF_  4096
#define B_   4
#define T_   1024
#define BT_  4096
#define V_   32000
#define QKVW 3072            // packed qkv width: H * 3 * D

// Activation scratch
__device__ __align__(16) float g_x[BT_ * E_];
__device__ __align__(16) float g_h[BT_ * E_];
__device__ __align__(16) float g_qkv[BT_ * QKVW];
__device__ __align__(16) float g_oc[BT_ * E_];
__device__ __align__(16) float g_ff[BT_ * FF_];
__device__ __align__(16) float g_rl[BT_];

// tf32-rounded weights
__device__ __align__(16) float g_wqkv[(size_t)L_ * E_ * QKVW];
__device__ __align__(16) float g_wp[L_ * E_ * E_];
__device__ __align__(16) float g_w1[(size_t)L_ * E_ * FF_];
__device__ __align__(16) float g_w2[(size_t)L_ * FF_ * E_];
__device__ __align__(16) float g_wh[(size_t)E_ * V_];

#define FLAG_RELU     4
#define FLAG_ROUND    16

__device__ __forceinline__ uint32_t f2tf(float f) {
    uint32_t u;
    asm("cvt.rna.tf32.f32 %0, %1;" : "=r"(u) : "f"(f));
    return u;
}
__device__ __forceinline__ float tfround(float f) { return __uint_as_float(f2tf(f)); }

__device__ __forceinline__ void cpa16(void* s, const void* g) {
    uint32_t sa = (uint32_t)__cvta_generic_to_shared(s);
    asm volatile("cp.async.cg.shared.global [%0], [%1], 16;\n" :: "r"(sa), "l"(g));
}
__device__ __forceinline__ void cpa_commit() { asm volatile("cp.async.commit_group;\n"); }
__device__ __forceinline__ void cpa_wait1()  { asm volatile("cp.async.wait_group 1;\n"); }
__device__ __forceinline__ void cpa_wait0()  { asm volatile("cp.async.wait_group 0;\n"); }

#define MMA_TF32(d0,d1,d2,d3,a0,a1,a2,a3,b0,b1) \
    asm volatile("mma.sync.aligned.m16n8k8.row.col.f32.tf32.tf32.f32 " \
        "{%0,%1,%2,%3}, {%4,%5,%6,%7}, {%8,%9}, {%0,%1,%2,%3};\n" \
        : "+f"(d0), "+f"(d1), "+f"(d2), "+f"(d3) \
        : "r"(a0), "r"(a1), "r"(a2), "r"(a3), "r"(b0), "r"(b1))

// ---------------------------------------------------------------------------
// tf32 GEMM (non-trans B), cp.async double-buffered, BK=32, 8 warps (2x4).
// ---------------------------------------------------------------------------
template<int BM, int BN>
__global__ __launch_bounds__(256, 2)
void mma_gemm(const float* __restrict__ A, int lda,
              const float* __restrict__ Bm, int ldb,
              float* __restrict__ C, int ldc,
              int M, int N, int K,
              const float* __restrict__ bias,
              const float* __restrict__ resid,
              int flags)
{
    constexpr int BK  = 32;
    constexpr int WM  = BM / 2;
    constexpr int WN  = BN / 4;
    constexpr int MI  = WM / 16;
    constexpr int NI  = WN / 8;
    constexpr int AST = 36;
    constexpr int BSTN = BN + 8;
    constexpr int ASZ = BM * AST;
    constexpr int BSZ = BK * BSTN;
    constexpr int AV  = BM * BK / (4 * 256);
    constexpr int BV  = BN * BK / (4 * 256);

    extern __shared__ __align__(16) float dsm[];
    float* Abuf = dsm;
    float* Bbuf = dsm + 2 * ASZ;

    const int row0 = blockIdx.y * BM;
    const int col0 = blockIdx.x * BN;
    const int tid  = threadIdx.x;
    const int warp = tid >> 5;
    const int lane = tid & 31;
    const int wm   = (warp >> 2) * WM;
    const int wn   = (warp & 3) * WN;
    const int qr   = lane >> 2;
    const int qc   = lane & 3;

    const int nk = K / BK;

    float acc[MI][NI][4];
#pragma unroll
    for (int i = 0; i < MI; i++)
#pragma unroll
        for (int j = 0; j < NI; j++)
#pragma unroll
            for (int t = 0; t < 4; t++) acc[i][j][t] = 0.f;

    auto issue = [&](int k0, int buf) {
        float* as = Abuf + buf * ASZ;
#pragma unroll
        for (int i = 0; i < AV; i++) {
            int e = tid + i * 256;
            int m = e >> 3, kq = e & 7;
            cpa16(&as[m * AST + kq * 4], A + (long long)(row0 + m) * lda + k0 + kq * 4);
        }
        float* bs = Bbuf + buf * BSZ;
#pragma unroll
        for (int i = 0; i < BV; i++) {
            int e = tid + i * 256;
            int kk = e / (BN / 4), nq = e % (BN / 4);
            cpa16(&bs[kk * BSTN + nq * 4], Bm + (long long)(k0 + kk) * ldb + col0 + nq * 4);
        }
        cpa_commit();
    };

    issue(0, 0);
    for (int it = 0; it < nk; it++) {
        if (it + 1 < nk) { issue((it + 1) * BK, (it + 1) & 1); cpa_wait1(); }
        else             { cpa_wait0(); }
        __syncthreads();

        const uint32_t* as = (const uint32_t*)(Abuf + (it & 1) * ASZ);
        const uint32_t* bs = (const uint32_t*)(Bbuf + (it & 1) * BSZ);

#pragma unroll
        for (int kt = 0; kt < 4; kt++) {
            const int kk = kt * 8;
            uint32_t a[MI][4];
#pragma unroll
            for (int mi = 0; mi < MI; mi++) {
                int r = wm + mi * 16 + qr;
                a[mi][0] = as[r * AST + kk + qc];
                a[mi][1] = as[(r + 8) * AST + kk + qc];
                a[mi][2] = as[r * AST + kk + qc + 4];
                a[mi][3] = as[(r + 8) * AST + kk + qc + 4];
            }
            uint32_t b[NI][2];
#pragma unroll
            for (int ni = 0; ni < NI; ni++) {
                int n = wn + ni * 8 + qr;
                b[ni][0] = bs[(kk + qc) * BSTN + n];
                b[ni][1] = bs[(kk + qc + 4) * BSTN + n];
            }
#pragma unroll
            for (int mi = 0; mi < MI; mi++)
#pragma unroll
                for (int ni = 0; ni < NI; ni++)
                    MMA_TF32(acc[mi][ni][0], acc[mi][ni][1], acc[mi][ni][2], acc[mi][ni][3],
                             a[mi][0], a[mi][1], a[mi][2], a[mi][3],
                             b[ni][0], b[ni][1]);
        }
        __syncthreads();
    }

#pragma unroll
    for (int mi = 0; mi < MI; mi++) {
#pragma unroll
        for (int ni = 0; ni < NI; ni++) {
#pragma unroll
            for (int half = 0; half < 2; half++) {
                int r = row0 + wm + mi * 16 + qr + half * 8;
                int c = col0 + wn + ni * 8 + qc * 2;
                float v0 = acc[mi][ni][half * 2];
                float v1 = acc[mi][ni][half * 2 + 1];
                if (bias) { v0 += bias[c]; v1 += bias[c + 1]; }
                if (resid) {
                    float2 rr = *(const float2*)(resid + (long long)r * ldc + c);
                    v0 += rr.x; v1 += rr.y;
                }
                if (flags & FLAG_RELU) { v0 = fmaxf(v0, 0.f); v1 = fmaxf(v1, 0.f); }
                if (flags & FLAG_ROUND) { v0 = tfround(v0); v1 = tfround(v1); }
                *(float2*)(C + (long long)r * ldc + c) = make_float2(v0, v1);
            }
        }
    }
}

// ---------------------------------------------------------------------------
// Fused causal flash attention. Grid (T/128, B*H), 256 threads.
// qkv packed [bt][h*192 + {q:0|k:64|v:128} + d]. Output -> oc[bt][h*64+d].
// ---------------------------------------------------------------------------
#define KST 68
#define VST 72
#define PST 68
#define KSZ (64 * KST)
#define VSZ (64 * VST)
#define FL_SMEM ((2 * KSZ + 2 * VSZ + 8 * 16 * PST) * 4)

__global__ __launch_bounds__(256, 2)
void flash_kernel(const float* __restrict__ qkv, float* __restrict__ oc)
{
    extern __shared__ __align__(16) float fsm[];
    float* Kb = fsm;                    // 2 * KSZ
    float* Vb = fsm + 2 * KSZ;          // 2 * VSZ
    float* Ps = fsm + 2 * KSZ + 2 * VSZ;

    const int row0 = blockIdx.x * 128;
    const int b    = blockIdx.y >> 4;
    const int h    = blockIdx.y & 15;
    const int tid  = threadIdx.x;
    const int wid  = tid >> 5;
    const int lane = tid & 31;
    const int qr   = lane >> 2;
    const int qc   = lane & 3;

    const float* base = qkv + (long long)b * T_ * QKVW + h * 192;
    const int r1 = row0 + wid * 16 + qr;
    const int r2 = r1 + 8;

    // Q fragments, pre-scaled by 2^-5 (exact in tf32)
    uint32_t aq[8][4];
#pragma unroll
    for (int kt = 0; kt < 8; kt++) {
        const float* q1 = base + (long long)r1 * QKVW + kt * 8;
        const float* q2 = base + (long long)r2 * QKVW + kt * 8;
        aq[kt][0] = f2tf(q1[qc]     * 0.03125f);
        aq[kt][1] = f2tf(q2[qc]     * 0.03125f);
        aq[kt][2] = f2tf(q1[qc + 4] * 0.03125f);
        aq[kt][3] = f2tf(q2[qc + 4] * 0.03125f);
    }

    float o[8][4];
#pragma unroll
    for (int nt = 0; nt < 8; nt++)
#pragma unroll
        for (int t = 0; t < 4; t++) o[nt][t] = 0.f;
    float m0 = -1e30f, m1 = -1e30f, l0 = 0.f, l1 = 0.f;

    const int ntiles = (row0 >> 6) + 2;   // key tiles of 64 up to diagonal

    auto issue = [&](int j, int buf) {
        // K tile: 64 rows x 16 float4
        float* ks = Kb + buf * KSZ;
        float* vs = Vb + buf * VSZ;
#pragma unroll
        for (int i = 0; i < 4; i++) {
            int e = tid + i * 256;
            int r = e >> 4, qd = e & 15;
            const float* src = base + (long long)(j * 64 + r) * QKVW;
            cpa16(&ks[r * KST + qd * 4], src + 64 + qd * 4);
            cpa16(&vs[r * VST + qd * 4], src + 128 + qd * 4);
        }
        cpa_commit();
    };

    issue(0, 0);
    for (int j = 0; j < ntiles; j++) {
        if (j + 1 < ntiles) { issue(j + 1, (j + 1) & 1); cpa_wait1(); }
        else                { cpa_wait0(); }
        __syncthreads();

        const uint32_t* ks = (const uint32_t*)(Kb + (j & 1) * KSZ);
        const uint32_t* vs = (const uint32_t*)(Vb + (j & 1) * VSZ);

        // ---- scores: S = Qs . K^T ----
        float s[8][4];
#pragma unroll
        for (int nt = 0; nt < 8; nt++)
#pragma unroll
            for (int t = 0; t < 4; t++) s[nt][t] = 0.f;
#pragma unroll
        for (int kt = 0; kt < 8; kt++) {
            const int kk = kt * 8;
            uint32_t bfr[8][2];
#pragma unroll
            for (int nt = 0; nt < 8; nt++) {
                bfr[nt][0] = ks[(nt * 8 + qr) * KST + kk + qc];
                bfr[nt][1] = ks[(nt * 8 + qr) * KST + kk + qc + 4];
            }
#pragma unroll
            for (int nt = 0; nt < 8; nt++)
                MMA_TF32(s[nt][0], s[nt][1], s[nt][2], s[nt][3],
                         aq[kt][0], aq[kt][1], aq[kt][2], aq[kt][3],
                         bfr[nt][0], bfr[nt][1]);
        }

        // ---- causal mask (only straddling tiles) ----
        if (j * 64 + 63 > row0 + wid * 16) {
#pragma unroll
            for (int nt = 0; nt < 8; nt++) {
                int c = j * 64 + nt * 8 + qc * 2;
                if (c     > r1) s[nt][0] = -1e30f;
                if (c + 1 > r1) s[nt][1] = -1e30f;
                if (c     > r2) s[nt][2] = -1e30f;
                if (c + 1 > r2) s[nt][3] = -1e30f;
            }
        }

        // ---- online softmax ----
        float nm0 = m0, nm1 = m1;
#pragma unroll
        for (int nt = 0; nt < 8; nt++) {
            nm0 = fmaxf(nm0, fmaxf(s[nt][0], s[nt][1]));
            nm1 = fmaxf(nm1, fmaxf(s[nt][2], s[nt][3]));
        }
        nm0 = fmaxf(nm0, __shfl_xor_sync(0xffffffff, nm0, 1));
        nm0 = fmaxf(nm0, __shfl_xor_sync(0xffffffff, nm0, 2));
        nm1 = fmaxf(nm1, __shfl_xor_sync(0xffffffff, nm1, 1));
        nm1 = fmaxf(nm1, __shfl_xor_sync(0xffffffff, nm1, 2));

        float f0 = __expf(m0 - nm0), f1 = __expf(m1 - nm1);
        m0 = nm0; m1 = nm1;

        float* pw = Ps + wid * 16 * PST;
        float rs0 = 0.f, rs1 = 0.f;
        __syncwarp();
#pragma unroll
        for (int nt = 0; nt < 8; nt++) {
            float p0 = __expf(s[nt][0] - nm0);
            float p1 = __expf(s[nt][1] - nm0);
            float p2 = __expf(s[nt][2] - nm1);
            float p3 = __expf(s[nt][3] - nm1);
            rs0 += p0 + p1; rs1 += p2 + p3;
            *(float2*)&pw[qr * PST + nt * 8 + qc * 2] =
                make_float2(__uint_as_float(f2tf(p0)), __uint_as_float(f2tf(p1)));
            *(float2*)&pw[(qr + 8) * PST + nt * 8 + qc * 2] =
                make_float2(__uint_as_float(f2tf(p2)), __uint_as_float(f2tf(p3)));
        }
        rs0 += __shfl_xor_sync(0xffffffff, rs0, 1);
        rs0 += __shfl_xor_sync(0xffffffff, rs0, 2);
        rs1 += __shfl_xor_sync(0xffffffff, rs1, 1);
        rs1 += __shfl_xor_sync(0xffffffff, rs1, 2);
        l0 = l0 * f0 + rs0;
        l1 = l1 * f1 + rs1;

#pragma unroll
        for (int nt = 0; nt < 8; nt++) {
            o[nt][0] *= f0; o[nt][1] *= f0;
            o[nt][2] *= f1; o[nt][3] *= f1;
        }
        __syncwarp();

        // ---- O += P . V ----
        const uint32_t* pr = (const uint32_t*)pw;
#pragma unroll
        for (int kt = 0; kt < 8; kt++) {
            const int kk = kt * 8;
            uint32_t a[4];
            a[0] = pr[qr * PST + kk + qc];
            a[1] = pr[(qr + 8) * PST + kk + qc];
            a[2] = pr[qr * PST + kk + qc + 4];
            a[3] = pr[(qr + 8) * PST + kk + qc + 4];
            uint32_t bfr[8][2];
#pragma unroll
            for (int nt = 0; nt < 8; nt++) {
                bfr[nt][0] = vs[(kk + qc) * VST + nt * 8 + qr];
                bfr[nt][1] = vs[(kk + qc + 4) * VST + nt * 8 + qr];
            }
#pragma unroll
            for (int nt = 0; nt < 8; nt++)
                MMA_TF32(o[nt][0], o[nt][1], o[nt][2], o[nt][3],
                         a[0], a[1], a[2], a[3], bfr[nt][0], bfr[nt][1]);
        }
        __syncthreads();
    }

    // ---- normalize + store (tf32-rounded; feeds proj GEMM) ----
    float i0 = 1.f / l0, i1 = 1.f / l1;
    float* o1 = oc + ((long long)b * T_ + r1) * E_ + h * 64;
    float* o2 = oc + ((long long)b * T_ + r2) * E_ + h * 64;
#pragma unroll
    for (int nt = 0; nt < 8; nt++) {
        int c = nt * 8 + qc * 2;
        *(float2*)(o1 + c) = make_float2(tfround(o[nt][0] * i0), tfround(o[nt][1] * i0));
        *(float2*)(o2 + c) = make_float2(tfround(o[nt][2] * i1), tfround(o[nt][3] * i1));
    }
}

// ---------------------------------------------------------------------------
__global__ void tf32_cvt_kernel(const float4* __restrict__ in, float4* __restrict__ out, int n4)
{
    int i = blockIdx.x * 256 + threadIdx.x;
    int stride = gridDim.x * 256;
    for (; i < n4; i += stride) {
        float4 f = in[i];
        f.x = tfround(f.x); f.y = tfround(f.y);
        f.z = tfround(f.z); f.w = tfround(f.w);
        out[i] = f;
    }
}

// Pack Wq/Wk/Wv [L][H][E][D] -> wqkv [L][E][h*192 + which*64 + d], tf32
__global__ void qkv_pack_kernel(const float* __restrict__ Wq,
                                const float* __restrict__ Wk,
                                const float* __restrict__ Wv,
                                float* __restrict__ wqkv)
{
    long long i = (long long)blockIdx.x * 256 + threadIdx.x;
    long long total = (long long)L_ * E_ * QKVW;
    long long stride = (long long)gridDim.x * 256;
    for (; i < total; i += stride) {
        int c  = (int)(i % QKVW);
        long long rem = i / QKVW;
        int e  = (int)(rem % E_);
        int l  = (int)(rem / E_);
        int hh = c / 192;
        int wsel = (c % 192) / 64;
        int d  = c % 64;
        long long src = (((long long)l * H_ + hh) * E_ + e) * D_ + d;
        float v = (wsel == 0) ? Wq[src] : (wsel == 1) ? Wk[src] : Wv[src];
        wqkv[i] = tfround(v);
    }
}

__global__ void embed_kernel(const int* __restrict__ idx,
                             const float* __restrict__ tok,
                             const float* __restrict__ pos,
                             float* __restrict__ x)
{
    int row = blockIdx.x;
    int t   = row & (T_ - 1);
    int tk  = idx[row];
    const float* te = tok + (long long)tk * E_;
    const float* pe = pos + (long long)t  * E_;
    float* xr = x + (long long)row * E_;
    for (int c = threadIdx.x; c < E_; c += blockDim.x)
        xr[c] = te[c] + pe[c];
}

__global__ void ln_kernel(const float* __restrict__ x, float* __restrict__ y,
                          const float* __restrict__ sc, const float* __restrict__ bi)
{
    int row = blockIdx.x;
    const float* xr = x + (long long)row * E_;
    float* yr = y + (long long)row * E_;
    float v[4];
    float sum = 0.f, sq = 0.f;
#pragma unroll
    for (int i = 0; i < 4; i++) {
        v[i] = xr[threadIdx.x + i * 256];
        sum += v[i]; sq += v[i] * v[i];
    }
    __shared__ float s1[256], s2[256];
    s1[threadIdx.x] = sum; s2[threadIdx.x] = sq;
    __syncthreads();
    for (int st = 128; st > 0; st >>= 1) {
        if (threadIdx.x < st) {
            s1[threadIdx.x] += s1[threadIdx.x + st];
            s2[threadIdx.x] += s2[threadIdx.x + st];
        }
        __syncthreads();
    }
    float mean = s1[0] * (1.f / E_);
    float var  = s2[0] * (1.f / E_) - mean * mean;
    float inv  = rsqrtf(var + 1e-5f);
#pragma unroll
    for (int i = 0; i < 4; i++) {
        int c = threadIdx.x + i * 256;
        yr[c] = tfround((v[i] - mean) * inv * sc[c] + bi[c]);
    }
}

__global__ void loss_rows_kernel(const float* __restrict__ logits,
                                 const int* __restrict__ tgt,
                                 float* __restrict__ rl)
{
    int row = blockIdx.x;
    const float4* lg4 = (const float4*)(logits + (long long)row * V_);
    int tid = threadIdx.x;
    float m = -1e30f;
    for (int c = tid; c < V_ / 4; c += 256) {
        float4 f = lg4[c];
        m = fmaxf(m, fmaxf(fmaxf(f.x, f.y), fmaxf(f.z, f.w)));
    }
    __shared__ float sm[256];
    sm[tid] = m; __syncthreads();
    for (int st = 128; st > 0; st >>= 1) {
        if (tid < st) sm[tid] = fmaxf(sm[tid], sm[tid + st]);
        __syncthreads();
    }
    m = sm[0];
    __syncthreads();
    float s = 0.f;
    for (int c = tid; c < V_ / 4; c += 256) {
        float4 f = lg4[c];
        s += __expf(f.x - m) + __expf(f.y - m) + __expf(f.z - m) + __expf(f.w - m);
    }
    sm[tid] = s; __syncthreads();
    for (int st = 128; st > 0; st >>= 1) {
        if (tid < st) sm[tid] += sm[tid + st];
        __syncthreads();
    }
    if (tid == 0) {
        const float* lg = logits + (long long)row * V_;
        float lse = m + __logf(sm[0]);
        int t = tgt[row];
        float ce = lse - lg[t];
        float w = 1.f;
        if (t == 4 || t == 3 || t == 1) w = 1.5f;
        if (t == 2) w = 2.0f;
        if (t == 0) w = 0.1f;
        rl[row] = ce * w;
    }
}

__global__ void loss_reduce_kernel(const float* __restrict__ rl, float* __restrict__ out)
{
    __shared__ float sm[1024];
    float s = 0.f;
    for (int i = threadIdx.x; i < BT_; i += 1024) s += rl[i];
    sm[threadIdx.x] = s;
    __syncthreads();
    for (int st = 512; st > 0; st >>= 1) {
        if (threadIdx.x < st) sm[threadIdx.x] += sm[threadIdx.x + st];
        __syncthreads();
    }
    if (threadIdx.x == 0) *out = sm[0] * (1.f / BT_);
}

// ---------------------------------------------------------------------------
#define SMEM_G128 ((2 * 128 * 36 + 2 * 32 * 136) * 4)

static inline void gemm128(const float* A, int lda,
                           const float* Bm, int ldb,
                           float* C, int ldc,
                           int M, int N, int K,
                           const float* bias, const float* resid, int flags)
{
    dim3 grid(N / 128, M / 128, 1);
    mma_gemm<128, 128><<<grid, 256, SMEM_G128>>>(A, lda, Bm, ldb, C, ldc,
                                                 M, N, K, bias, resid, flags);
}

extern "C" void kernel_launch(void* const* d_in, const int* in_sizes, int n_in,
                              void* d_out, int out_size)
{
    const int*   idx = (const int*)d_in[0];
    const int*   tgt = (const int*)d_in[1];
    const float* tok = (const float*)d_in[2];
    const float* pos = (const float*)d_in[3];
    const float* Wq  = (const float*)d_in[4];
    const float* Wk  = (const float*)d_in[5];
    const float* Wv  = (const float*)d_in[6];
    const float* Wp  = (const float*)d_in[7];
    const float* bp  = (const float*)d_in[8];
    const float* W1  = (const float*)d_in[9];
    const float* b1  = (const float*)d_in[10];
    const float* W2  = (const float*)d_in[11];
    const float* b2  = (const float*)d_in[12];
    const float* l1s = (const float*)d_in[13];
    const float* l1b = (const float*)d_in[14];
    const float* l2s = (const float*)d_in[15];
    const float* l2b = (const float*)d_in[16];
    const float* lfs = (const float*)d_in[17];
    const float* lfb = (const float*)d_in[18];
    const float* Wh  = (const float*)d_in[19];
    const float* bh  = (const float*)d_in[20];
    float* out = (float*)d_out;

    cudaFuncSetAttribute(mma_gemm<128, 128>,
                         cudaFuncAttributeMaxDynamicSharedMemorySize, SMEM_G128);
    cudaFuncSetAttribute(flash_kernel,
                         cudaFuncAttributeMaxDynamicSharedMemorySize, FL_SMEM);

    float *x, *h, *qkv, *oc, *ff, *rl;
    float *wqkv, *wp, *w1, *w2, *wh;
    cudaGetSymbolAddress((void**)&x,    g_x);
    cudaGetSymbolAddress((void**)&h,    g_h);
    cudaGetSymbolAddress((void**)&qkv,  g_qkv);
    cudaGetSymbolAddress((void**)&oc,   g_oc);
    cudaGetSymbolAddress((void**)&ff,   g_ff);
    cudaGetSymbolAddress((void**)&rl,   g_rl);
    cudaGetSymbolAddress((void**)&wqkv, g_wqkv);
    cudaGetSymbolAddress((void**)&wp,   g_wp);
    cudaGetSymbolAddress((void**)&w1,   g_w1);
    cudaGetSymbolAddress((void**)&w2,   g_w2);
    cudaGetSymbolAddress((void**)&wh,   g_wh);

    // Weight prep
    qkv_pack_kernel<<<4096, 256>>>(Wq, Wk, Wv, wqkv);
    tf32_cvt_kernel<<<2048, 256>>>((const float4*)Wp, (float4*)wp, L_ * E_ * E_ / 4);
    tf32_cvt_kernel<<<2048, 256>>>((const float4*)W1, (float4*)w1, L_ * E_ * FF_ / 4);
    tf32_cvt_kernel<<<2048, 256>>>((const float4*)W2, (float4*)w2, L_ * FF_ * E_ / 4);
    tf32_cvt_kernel<<<2048, 256>>>((const float4*)Wh, (float4*)wh, E_ * V_ / 4);

    embed_kernel<<<BT_, 256>>>(idx, tok, pos, x);

    for (int l = 0; l < L_; l++) {
        ln_kernel<<<BT_, 256>>>(x, h, l1s + l * E_, l1b + l * E_);

        // QKV: one fat GEMM [BT, 3072]
        gemm128(h, E_, wqkv + (long long)l * E_ * QKVW, QKVW, qkv, QKVW,
                BT_, QKVW, E_, nullptr, nullptr, FLAG_ROUND);

        // Fused attention -> oc (concat layout)
        flash_kernel<<<dim3(T_ / 128, B_ * H_), 256, FL_SMEM>>>(qkv, oc);

        // x = x + oc @ Wproj + bproj
        gemm128(oc, E_, wp + (long long)l * E_ * E_, E_, x, E_,
                BT_, E_, E_, bp + l * E_, x, 0);

        ln_kernel<<<BT_, 256>>>(x, h, l2s + l * E_, l2b + l * E_);

        gemm128(h, E_, w1 + (long long)l * E_ * FF_, FF_, ff, FF_,
                BT_, FF_, E_, b1 + l * FF_, nullptr, FLAG_RELU | FLAG_ROUND);

        gemm128(ff, FF_, w2 + (long long)l * FF_ * E_, E_, x, E_,
                BT_, E_, FF_, b2 + l * E_, x, 0);
    }

    ln_kernel<<<BT_, 256>>>(x, h, lfs, lfb);
    gemm128(h, E_, wh, V_, out, V_,
            BT_, V_, E_, bh, nullptr, 0);

    loss_rows_kernel<<<BT_, 256>>>(out, tgt, rl);
    if ((long long)out_size >= (long long)BT_ * V_ + 1)
        loss_reduce_kernel<<<1, 1024>>>(rl, out + (long long)BT_ * V_);
}

// round 8
// speedup vs baseline: 6.9752x; 1.0763x over previous
#include <cuda_runtime.h>
#include <math.h>
#include <stdint.h>

// Problem config
#define E_   1024
#define H_   16
#define D_   64
#define L_   6
#define FF_  4096
#define B_   4
#define T_   1024
#define BT_  4096
#define V_   32000
#define QKVW 3072

// Activation scratch
__device__ __align__(16) float g_x[BT_ * E_];
__device__ __align__(16) float g_h[BT_ * E_];
__device__ __align__(16) float g_qkv[BT_ * QKVW];
__device__ __align__(16) float g_oc[BT_ * E_];
__device__ __align__(16) float g_ff[BT_ * FF_];
__device__ __align__(16) float g_rl[BT_];

// Fragment-packed tf32 weights (tile = 32k x 128n = 4096 words in mma-frag order)
__device__ __align__(16) float g_wqkv[(size_t)L_ * E_ * QKVW];
__device__ __align__(16) float g_wp[L_ * E_ * E_];
__device__ __align__(16) float g_w1[(size_t)L_ * E_ * FF_];
__device__ __align__(16) float g_w2[(size_t)L_ * FF_ * E_];
__device__ __align__(16) float g_wh[(size_t)E_ * V_];

#define FLAG_RELU     4
#define FLAG_ROUND    16

__device__ __forceinline__ uint32_t f2tf(float f) {
    uint32_t u;
    asm("cvt.rna.tf32.f32 %0, %1;" : "=r"(u) : "f"(f));
    return u;
}
__device__ __forceinline__ float tfround(float f) { return __uint_as_float(f2tf(f)); }

__device__ __forceinline__ void cpa16(void* s, const void* g) {
    uint32_t sa = (uint32_t)__cvta_generic_to_shared(s);
    asm volatile("cp.async.cg.shared.global [%0], [%1], 16;\n" :: "r"(sa), "l"(g));
}
__device__ __forceinline__ void cpa_commit() { asm volatile("cp.async.commit_group;\n"); }
template<int N> __device__ __forceinline__ void cpa_wait() {
    asm volatile("cp.async.wait_group %0;\n" :: "n"(N));
}

#define MMA_TF32(d0,d1,d2,d3,a0,a1,a2,a3,b0,b1) \
    asm volatile("mma.sync.aligned.m16n8k8.row.col.f32.tf32.tf32.f32 " \
        "{%0,%1,%2,%3}, {%4,%5,%6,%7}, {%8,%9}, {%0,%1,%2,%3};\n" \
        : "+f"(d0), "+f"(d1), "+f"(d2), "+f"(d3) \
        : "r"(a0), "r"(a1), "r"(a2), "r"(a3), "r"(b0), "r"(b1))

// ---------------------------------------------------------------------------
// tf32 GEMM: A row-major fp32(tf32-rounded), B fragment-packed weights.
// 128x128 tile, BK=32, 3-stage cp.async, 8 warps (2x4).
// ---------------------------------------------------------------------------
#define AST 36
#define ASZ (128 * AST)          // 4608 words
#define BSZ 4096                 // one packed tile
#define G_SMEM ((3 * ASZ + 3 * BSZ) * 4)

__global__ __launch_bounds__(256, 2)
void mma_gemm(const float* __restrict__ A, int lda,
              const float* __restrict__ Bp,
              float* __restrict__ C, int ldc,
              int M, int N, int K,
              const float* __restrict__ bias,
              const float* __restrict__ resid,
              int flags)
{
    extern __shared__ __align__(16) float dsm[];
    float* Abuf = dsm;             // 3 * ASZ
    float* Bbuf = dsm + 3 * ASZ;   // 3 * BSZ

    const int row0 = blockIdx.y * 128;
    const int col0 = blockIdx.x * 128;
    const int tid  = threadIdx.x;
    const int warp = tid >> 5;
    const int lane = tid & 31;
    const int wm   = (warp >> 2) * 64;
    const int wn8  = (warp & 3) * 4;       // B subtile base (n/8)
    const int qr   = lane >> 2;
    const int qc   = lane & 3;

    const int ntn    = N >> 7;             // packed tiles per k-row
    const int colblk = col0 >> 7;
    const int nk     = K >> 5;

    float acc[4][4][4];
#pragma unroll
    for (int i = 0; i < 4; i++)
#pragma unroll
        for (int j = 0; j < 4; j++)
#pragma unroll
            for (int t = 0; t < 4; t++) acc[i][j][t] = 0.f;

    auto issue = [&](int it) {
        int buf = it % 3;
        int k0  = it * 32;
        float* as = Abuf + buf * ASZ;
#pragma unroll
        for (int i = 0; i < 4; i++) {
            int e = tid + i * 256;
            int m = e >> 3, kq = e & 7;
            cpa16(&as[m * AST + kq * 4], A + (long long)(row0 + m) * lda + k0 + kq * 4);
        }
        float* bs = Bbuf + buf * BSZ;
        const float* bt = Bp + ((long long)(it) * ntn + colblk) * BSZ;
#pragma unroll
        for (int i = 0; i < 4; i++) {
            int o4 = tid + i * 256;
            cpa16(&bs[o4 * 4], bt + o4 * 4);
        }
        cpa_commit();
    };

    issue(0);
    if (nk > 1) issue(1);

    for (int it = 0; it < nk; it++) {
        if (it + 2 < nk) issue(it + 2);
        else             cpa_commit();      // empty group keeps count in step
        cpa_wait<2>();
        __syncthreads();

        const uint32_t* as = (const uint32_t*)(Abuf + (it % 3) * ASZ);
        const uint32_t* bs = (const uint32_t*)(Bbuf + (it % 3) * BSZ);

#pragma unroll
        for (int kt = 0; kt < 4; kt++) {
            const int kk = kt * 8;
            uint32_t a[4][4];
#pragma unroll
            for (int mi = 0; mi < 4; mi++) {
                int r = wm + mi * 16 + qr;
                a[mi][0] = as[r * AST + kk + qc];
                a[mi][1] = as[(r + 8) * AST + kk + qc];
                a[mi][2] = as[r * AST + kk + qc + 4];
                a[mi][3] = as[(r + 8) * AST + kk + qc + 4];
            }
            uint32_t b[4][2];
#pragma unroll
            for (int ni = 0; ni < 4; ni++) {
                uint2 t2 = *(const uint2*)&bs[(wn8 + ni) * 256 + kt * 64 + lane * 2];
                b[ni][0] = t2.x; b[ni][1] = t2.y;
            }
#pragma unroll
            for (int mi = 0; mi < 4; mi++)
#pragma unroll
                for (int ni = 0; ni < 4; ni++)
                    MMA_TF32(acc[mi][ni][0], acc[mi][ni][1], acc[mi][ni][2], acc[mi][ni][3],
                             a[mi][0], a[mi][1], a[mi][2], a[mi][3],
                             b[ni][0], b[ni][1]);
        }
        __syncthreads();
    }

#pragma unroll
    for (int mi = 0; mi < 4; mi++) {
#pragma unroll
        for (int ni = 0; ni < 4; ni++) {
#pragma unroll
            for (int half = 0; half < 2; half++) {
                int r = row0 + wm + mi * 16 + qr + half * 8;
                int c = col0 + (warp & 3) * 32 + ni * 8 + qc * 2;
                float v0 = acc[mi][ni][half * 2];
                float v1 = acc[mi][ni][half * 2 + 1];
                if (bias) { v0 += bias[c]; v1 += bias[c + 1]; }
                if (resid) {
                    float2 rr = *(const float2*)(resid + (long long)r * ldc + c);
                    v0 += rr.x; v1 += rr.y;
                }
                if (flags & FLAG_RELU) { v0 = fmaxf(v0, 0.f); v1 = fmaxf(v1, 0.f); }
                if (flags & FLAG_ROUND) { v0 = tfround(v0); v1 = tfround(v1); }
                *(float2*)(C + (long long)r * ldc + c) = make_float2(v0, v1);
            }
        }
    }
}

// ---------------------------------------------------------------------------
// Weight packing: [K,N] fp32 -> fragment-packed tf32 tiles.
// Tile (kt,nt): 4096 words in order [ns(16)][kt4(4)][lane(32)][s(2)]:
//   word(lane,s) = W[kt*32 + kt4*8 + (lane&3) + 4s][nt*128 + ns*8 + (lane>>2)]
// ---------------------------------------------------------------------------
__global__ __launch_bounds__(256)
void pack_w_kernel(const float* __restrict__ src, float* __restrict__ dst,
                   int N, int K)
{
    const int nt = blockIdx.x, kt = blockIdx.y, l = blockIdx.z;
    src += (long long)l * K * N;
    dst += (long long)l * K * N;
    __shared__ float sm[32][132];
    const int tid = threadIdx.x;
#pragma unroll
    for (int i = 0; i < 4; i++) {
        int e = tid + i * 256;
        int r = e >> 5, c4 = e & 31;
        float4 f = *(const float4*)(src + (long long)(kt * 32 + r) * N + nt * 128 + c4 * 4);
        sm[r][c4 * 4 + 0] = tfround(f.x);
        sm[r][c4 * 4 + 1] = tfround(f.y);
        sm[r][c4 * 4 + 2] = tfround(f.z);
        sm[r][c4 * 4 + 3] = tfround(f.w);
    }
    __syncthreads();
    float* o = dst + ((long long)kt * (N >> 7) + nt) * 4096;
#pragma unroll
    for (int i = 0; i < 4; i++) {
        int w4 = tid + i * 256;
        int w  = w4 * 4;
        int l2 = (w >> 1) & 31;            // even lane
        int ns = w >> 8;
        int k4 = (w >> 6) & 3;
        int kb = k4 * 8 + (l2 & 3);
        int nb = ns * 8 + (l2 >> 2);
        float4 f;
        f.x = sm[kb][nb];
        f.y = sm[kb + 4][nb];
        f.z = sm[kb + 1][nb];
        f.w = sm[kb + 5][nb];
        *(float4*)&o[w] = f;
    }
}

// QKV pack: gather from Wq/Wk/Wv [L][H][E][D] into packed wqkv (N=3072 cols:
// n = h*192 + sel*64 + d), fragment-packed + tf32.
__global__ __launch_bounds__(256)
void pack_qkv_kernel(const float* __restrict__ Wq,
                     const float* __restrict__ Wk,
                     const float* __restrict__ Wv,
                     float* __restrict__ dst)
{
    const int nt = blockIdx.x, kt = blockIdx.y, l = blockIdx.z;
    __shared__ float sm[32][132];
    const int tid = threadIdx.x;
#pragma unroll
    for (int i = 0; i < 4; i++) {
        int e = tid + i * 256;
        int r = e >> 5, c4 = e & 31;
        int n = nt * 128 + c4 * 4;
        int h = n / 192;
        int rem = n - h * 192;
        int sel = rem >> 6;
        int d = rem & 63;
        const float* W = (sel == 0) ? Wq : (sel == 1) ? Wk : Wv;
        float4 f = *(const float4*)(W + (((long long)l * H_ + h) * E_ + kt * 32 + r) * D_ + d);
        sm[r][c4 * 4 + 0] = tfround(f.x);
        sm[r][c4 * 4 + 1] = tfround(f.y);
        sm[r][c4 * 4 + 2] = tfround(f.z);
        sm[r][c4 * 4 + 3] = tfround(f.w);
    }
    __syncthreads();
    float* o = dst + (long long)l * E_ * QKVW + ((long long)kt * (QKVW >> 7) + nt) * 4096;
#pragma unroll
    for (int i = 0; i < 4; i++) {
        int w4 = tid + i * 256;
        int w  = w4 * 4;
        int l2 = (w >> 1) & 31;
        int ns = w >> 8;
        int k4 = (w >> 6) & 3;
        int kb = k4 * 8 + (l2 & 3);
        int nb = ns * 8 + (l2 >> 2);
        float4 f;
        f.x = sm[kb][nb];
        f.y = sm[kb + 4][nb];
        f.z = sm[kb + 1][nb];
        f.w = sm[kb + 5][nb];
        *(float4*)&o[w] = f;
    }
}

// ---------------------------------------------------------------------------
// Fused causal flash attention (unchanged from R7).
// ---------------------------------------------------------------------------
#define KST 68
#define VST 72
#define PST 68
#define KSZ (64 * KST)
#define VSZ (64 * VST)
#define FL_SMEM ((2 * KSZ + 2 * VSZ + 8 * 16 * PST) * 4)

__global__ __launch_bounds__(256, 2)
void flash_kernel(const float* __restrict__ qkv, float* __restrict__ oc)
{
    extern __shared__ __align__(16) float fsm[];
    float* Kb = fsm;
    float* Vb = fsm + 2 * KSZ;
    float* Ps = fsm + 2 * KSZ + 2 * VSZ;

    const int row0 = blockIdx.x * 128;
    const int b    = blockIdx.y >> 4;
    const int h    = blockIdx.y & 15;
    const int tid  = threadIdx.x;
    const int wid  = tid >> 5;
    const int lane = tid & 31;
    const int qr   = lane >> 2;
    const int qc   = lane & 3;

    const float* base = qkv + (long long)b * T_ * QKVW + h * 192;
    const int r1 = row0 + wid * 16 + qr;
    const int r2 = r1 + 8;

    uint32_t aq[8][4];
#pragma unroll
    for (int kt = 0; kt < 8; kt++) {
        const float* q1 = base + (long long)r1 * QKVW + kt * 8;
        const float* q2 = base + (long long)r2 * QKVW + kt * 8;
        aq[kt][0] = f2tf(q1[qc]     * 0.03125f);
        aq[kt][1] = f2tf(q2[qc]     * 0.03125f);
        aq[kt][2] = f2tf(q1[qc + 4] * 0.03125f);
        aq[kt][3] = f2tf(q2[qc + 4] * 0.03125f);
    }

    float o[8][4];
#pragma unroll
    for (int nt = 0; nt < 8; nt++)
#pragma unroll
        for (int t = 0; t < 4; t++) o[nt][t] = 0.f;
    float m0 = -1e30f, m1 = -1e30f, l0 = 0.f, l1 = 0.f;

    const int ntiles = (row0 >> 6) + 2;

    auto issue = [&](int j, int buf) {
        float* ks = Kb + buf * KSZ;
        float* vs = Vb + buf * VSZ;
#pragma unroll
        for (int i = 0; i < 4; i++) {
            int e = tid + i * 256;
            int r = e >> 4, qd = e & 15;
            const float* src = base + (long long)(j * 64 + r) * QKVW;
            cpa16(&ks[r * KST + qd * 4], src + 64 + qd * 4);
            cpa16(&vs[r * VST + qd * 4], src + 128 + qd * 4);
        }
        cpa_commit();
    };

    issue(0, 0);
    for (int j = 0; j < ntiles; j++) {
        if (j + 1 < ntiles) { issue(j + 1, (j + 1) & 1); cpa_wait<1>(); }
        else                { cpa_wait<0>(); }
        __syncthreads();

        const uint32_t* ks = (const uint32_t*)(Kb + (j & 1) * KSZ);
        const uint32_t* vs = (const uint32_t*)(Vb + (j & 1) * VSZ);

        float s[8][4];
#pragma unroll
        for (int nt = 0; nt < 8; nt++)
#pragma unroll
            for (int t = 0; t < 4; t++) s[nt][t] = 0.f;
#pragma unroll
        for (int kt = 0; kt < 8; kt++) {
            const int kk = kt * 8;
            uint32_t bfr[8][2];
#pragma unroll
            for (int nt = 0; nt < 8; nt++) {
                bfr[nt][0] = ks[(nt * 8 + qr) * KST + kk + qc];
                bfr[nt][1] = ks[(nt * 8 + qr) * KST + kk + qc + 4];
            }
#pragma unroll
            for (int nt = 0; nt < 8; nt++)
                MMA_TF32(s[nt][0], s[nt][1], s[nt][2], s[nt][3],
                         aq[kt][0], aq[kt][1], aq[kt][2], aq[kt][3],
                         bfr[nt][0], bfr[nt][1]);
        }

        if (j * 64 + 63 > row0 + wid * 16) {
#pragma unroll
            for (int nt = 0; nt < 8; nt++) {
                int c = j * 64 + nt * 8 + qc * 2;
                if (c     > r1) s[nt][0] = -1e30f;
                if (c + 1 > r1) s[nt][1] = -1e30f;
                if (c     > r2) s[nt][2] = -1e30f;
                if (c + 1 > r2) s[nt][3] = -1e30f;
            }
        }

        float nm0 = m0, nm1 = m1;
#pragma unroll
        for (int nt = 0; nt < 8; nt++) {
            nm0 = fmaxf(nm0, fmaxf(s[nt][0], s[nt][1]));
            nm1 = fmaxf(nm1, fmaxf(s[nt][2], s[nt][3]));
        }
        nm0 = fmaxf(nm0, __shfl_xor_sync(0xffffffff, nm0, 1));
        nm0 = fmaxf(nm0, __shfl_xor_sync(0xffffffff, nm0, 2));
        nm1 = fmaxf(nm1, __shfl_xor_sync(0xffffffff, nm1, 1));
        nm1 = fmaxf(nm1, __shfl_xor_sync(0xffffffff, nm1, 2));

        float f0 = __expf(m0 - nm0), f1 = __expf(m1 - nm1);
        m0 = nm0; m1 = nm1;

        float* pw = Ps + wid * 16 * PST;
        float rs0 = 0.f, rs1 = 0.f;
        __syncwarp();
#pragma unroll
        for (int nt = 0; nt < 8; nt++) {
            float p0 = __expf(s[nt][0] - nm0);
            float p1 = __expf(s[nt][1] - nm0);
            float p2 = __expf(s[nt][2] - nm1);
            float p3 = __expf(s[nt][3] - nm1);
            rs0 += p0 + p1; rs1 += p2 + p3;
            *(float2*)&pw[qr * PST + nt * 8 + qc * 2] =
                make_float2(__uint_as_float(f2tf(p0)), __uint_as_float(f2tf(p1)));
            *(float2*)&pw[(qr + 8) * PST + nt * 8 + qc * 2] =
                make_float2(__uint_as_float(f2tf(p2)), __uint_as_float(f2tf(p3)));
        }
        rs0 += __shfl_xor_sync(0xffffffff, rs0, 1);
        rs0 += __shfl_xor_sync(0xffffffff, rs0, 2);
        rs1 += __shfl_xor_sync(0xffffffff, rs1, 1);
        rs1 += __shfl_xor_sync(0xffffffff, rs1, 2);
        l0 = l0 * f0 + rs0;
        l1 = l1 * f1 + rs1;

#pragma unroll
        for (int nt = 0; nt < 8; nt++) {
            o[nt][0] *= f0; o[nt][1] *= f0;
            o[nt][2] *= f1; o[nt][3] *= f1;
        }
        __syncwarp();

        const uint32_t* pr = (const uint32_t*)pw;
#pragma unroll
        for (int kt = 0; kt < 8; kt++) {
            const int kk = kt * 8;
            uint32_t a[4];
            a[0] = pr[qr * PST + kk + qc];
            a[1] = pr[(qr + 8) * PST + kk + qc];
            a[2] = pr[qr * PST + kk + qc + 4];
            a[3] = pr[(qr + 8) * PST + kk + qc + 4];
            uint32_t bfr[8][2];
#pragma unroll
            for (int nt = 0; nt < 8; nt++) {
                bfr[nt][0] = vs[(kk + qc) * VST + nt * 8 + qr];
                bfr[nt][1] = vs[(kk + qc + 4) * VST + nt * 8 + qr];
            }
#pragma unroll
            for (int nt = 0; nt < 8; nt++)
                MMA_TF32(o[nt][0], o[nt][1], o[nt][2], o[nt][3],
                         a[0], a[1], a[2], a[3], bfr[nt][0], bfr[nt][1]);
        }
        __syncthreads();
    }

    float i0 = 1.f / l0, i1 = 1.f / l1;
    float* o1 = oc + ((long long)b * T_ + r1) * E_ + h * 64;
    float* o2 = oc + ((long long)b * T_ + r2) * E_ + h * 64;
#pragma unroll
    for (int nt = 0; nt < 8; nt++) {
        int c = nt * 8 + qc * 2;
        *(float2*)(o1 + c) = make_float2(tfround(o[nt][0] * i0), tfround(o[nt][1] * i0));
        *(float2*)(o2 + c) = make_float2(tfround(o[nt][2] * i1), tfround(o[nt][3] * i1));
    }
}

// ---------------------------------------------------------------------------
__global__ void embed_kernel(const int* __restrict__ idx,
                             const float* __restrict__ tok,
                             const float* __restrict__ pos,
                             float* __restrict__ x)
{
    int row = blockIdx.x;
    int t   = row & (T_ - 1);
    int tk  = idx[row];
    const float* te = tok + (long long)tk * E_;
    const float* pe = pos + (long long)t  * E_;
    float* xr = x + (long long)row * E_;
    for (int c = threadIdx.x; c < E_; c += blockDim.x)
        xr[c] = te[c] + pe[c];
}

__global__ void ln_kernel(const float* __restrict__ x, float* __restrict__ y,
                          const float* __restrict__ sc, const float* __restrict__ bi)
{
    int row = blockIdx.x;
    const float* xr = x + (long long)row * E_;
    float* yr = y + (long long)row * E_;
    float v[4];
    float sum = 0.f, sq = 0.f;
#pragma unroll
    for (int i = 0; i < 4; i++) {
        v[i] = xr[threadIdx.x + i * 256];
        sum += v[i]; sq += v[i] * v[i];
    }
    __shared__ float s1[256], s2[256];
    s1[threadIdx.x] = sum; s2[threadIdx.x] = sq;
    __syncthreads();
    for (int st = 128; st > 0; st >>= 1) {
        if (threadIdx.x < st) {
            s1[threadIdx.x] += s1[threadIdx.x + st];
            s2[threadIdx.x] += s2[threadIdx.x + st];
        }
        __syncthreads();
    }
    float mean = s1[0] * (1.f / E_);
    float var  = s2[0] * (1.f / E_) - mean * mean;
    float inv  = rsqrtf(var + 1e-5f);
#pragma unroll
    for (int i = 0; i < 4; i++) {
        int c = threadIdx.x + i * 256;
        yr[c] = tfround((v[i] - mean) * inv * sc[c] + bi[c]);
    }
}

__global__ void loss_rows_kernel(const float* __restrict__ logits,
                                 const int* __restrict__ tgt,
                                 float* __restrict__ rl)
{
    int row = blockIdx.x;
    const float4* lg4 = (const float4*)(logits + (long long)row * V_);
    int tid = threadIdx.x;
    float m = -1e30f;
    for (int c = tid; c < V_ / 4; c += 256) {
        float4 f = lg4[c];
        m = fmaxf(m, fmaxf(fmaxf(f.x, f.y), fmaxf(f.z, f.w)));
    }
    __shared__ float sm[256];
    sm[tid] = m; __syncthreads();
    for (int st = 128; st > 0; st >>= 1) {
        if (tid < st) sm[tid] = fmaxf(sm[tid], sm[tid + st]);
        __syncthreads();
    }
    m = sm[0];
    __syncthreads();
    float s = 0.f;
    for (int c = tid; c < V_ / 4; c += 256) {
        float4 f = lg4[c];
        s += __expf(f.x - m) + __expf(f.y - m) + __expf(f.z - m) + __expf(f.w - m);
    }
    sm[tid] = s; __syncthreads();
    for (int st = 128; st > 0; st >>= 1) {
        if (tid < st) sm[tid] += sm[tid + st];
        __syncthreads();
    }
    if (tid == 0) {
        const float* lg = logits + (long long)row * V_;
        float lse = m + __logf(sm[0]);
        int t = tgt[row];
        float ce = lse - lg[t];
        float w = 1.f;
        if (t == 4 || t == 3 || t == 1) w = 1.5f;
        if (t == 2) w = 2.0f;
        if (t == 0) w = 0.1f;
        rl[row] = ce * w;
    }
}

__global__ void loss_reduce_kernel(const float* __restrict__ rl, float* __restrict__ out)
{
    __shared__ float sm[1024];
    float s = 0.f;
    for (int i = threadIdx.x; i < BT_; i += 1024) s += rl[i];
    sm[threadIdx.x] = s;
    __syncthreads();
    for (int st = 512; st > 0; st >>= 1) {
        if (threadIdx.x < st) sm[threadIdx.x] += sm[threadIdx.x + st];
        __syncthreads();
    }
    if (threadIdx.x == 0) *out = sm[0] * (1.f / BT_);
}

// ---------------------------------------------------------------------------
static inline void gemm128(const float* A, int lda,
                           const float* Bp,
                           float* C, int ldc,
                           int M, int N, int K,
                           const float* bias, const float* resid, int flags)
{
    dim3 grid(N / 128, M / 128, 1);
    mma_gemm<<<grid, 256, G_SMEM>>>(A, lda, Bp, C, ldc, M, N, K, bias, resid, flags);
}

extern "C" void kernel_launch(void* const* d_in, const int* in_sizes, int n_in,
                              void* d_out, int out_size)
{
    const int*   idx = (const int*)d_in[0];
    const int*   tgt = (const int*)d_in[1];
    const float* tok = (const float*)d_in[2];
    const float* pos = (const float*)d_in[3];
    const float* Wq  = (const float*)d_in[4];
    const float* Wk  = (const float*)d_in[5];
    const float* Wv  = (const float*)d_in[6];
    const float* Wp  = (const float*)d_in[7];
    const float* bp  = (const float*)d_in[8];
    const float* W1  = (const float*)d_in[9];
    const float* b1  = (const float*)d_in[10];
    const float* W2  = (const float*)d_in[11];
    const float* b2  = (const float*)d_in[12];
    const float* l1s = (const float*)d_in[13];
    const float* l1b = (const float*)d_in[14];
    const float* l2s = (const float*)d_in[15];
    const float* l2b = (const float*)d_in[16];
    const float* lfs = (const float*)d_in[17];
    const float* lfb = (const float*)d_in[18];
    const float* Wh  = (const float*)d_in[19];
    const float* bh  = (const float*)d_in[20];
    float* out = (float*)d_out;

    cudaFuncSetAttribute(mma_gemm, cudaFuncAttributeMaxDynamicSharedMemorySize, G_SMEM);
    cudaFuncSetAttribute(flash_kernel, cudaFuncAttributeMaxDynamicSharedMemorySize, FL_SMEM);

    float *x, *h, *qkv, *oc, *ff, *rl;
    float *wqkv, *wp, *w1, *w2, *wh;
    cudaGetSymbolAddress((void**)&x,    g_x);
    cudaGetSymbolAddress((void**)&h,    g_h);
    cudaGetSymbolAddress((void**)&qkv,  g_qkv);
    cudaGetSymbolAddress((void**)&oc,   g_oc);
    cudaGetSymbolAddress((void**)&ff,   g_ff);
    cudaGetSymbolAddress((void**)&rl,   g_rl);
    cudaGetSymbolAddress((void**)&wqkv, g_wqkv);
    cudaGetSymbolAddress((void**)&wp,   g_wp);
    cudaGetSymbolAddress((void**)&w1,   g_w1);
    cudaGetSymbolAddress((void**)&w2,   g_w2);
    cudaGetSymbolAddress((void**)&wh,   g_wh);

    // Weight prep (fragment-packed tf32)
    pack_qkv_kernel<<<dim3(QKVW / 128, E_ / 32, L_), 256>>>(Wq, Wk, Wv, wqkv);
    pack_w_kernel<<<dim3(E_ / 128, E_ / 32, L_), 256>>>(Wp, wp, E_, E_);
    pack_w_kernel<<<dim3(FF_ / 128, E_ / 32, L_), 256>>>(W1, w1, FF_, E_);
    pack_w_kernel<<<dim3(E_ / 128, FF_ / 32, L_), 256>>>(W2, w2, E_, FF_);
    pack_w_kernel<<<dim3(V_ / 128, E_ / 32, 1), 256>>>(Wh, wh, V_, E_);

    embed_kernel<<<BT_, 256>>>(idx, tok, pos, x);

    for (int l = 0; l < L_; l++) {
        ln_kernel<<<BT_, 256>>>(x, h, l1s + l * E_, l1b + l * E_);

        gemm128(h, E_, wqkv + (long long)l * E_ * QKVW, qkv, QKVW,
                BT_, QKVW, E_, nullptr, nullptr, FLAG_ROUND);

        flash_kernel<<<dim3(T_ / 128, B_ * H_), 256, FL_SMEM>>>(qkv, oc);

        gemm128(oc, E_, wp + (long long)l * E_ * E_, x, E_,
                BT_, E_, E_, bp + l * E_, x, 0);

        ln_kernel<<<BT_, 256>>>(x, h, l2s + l * E_, l2b + l * E_);

        gemm128(h, E_, w1 + (long long)l * E_ * FF_, ff, FF_,
                BT_, FF_, E_, b1 + l * FF_, nullptr, FLAG_RELU | FLAG_ROUND);

        gemm128(ff, FF_, w2 + (long long)l * FF_ * E_, x, E_,
                BT_, E_, FF_, b2 + l * E_, x, 0);
    }

    ln_kernel<<<BT_, 256>>>(x, h, lfs, lfb);
    gemm128(h, E_, wh, out, V_,
            BT_, V_, E_, bh, nullptr, 0);

    loss_rows_kernel<<<BT_, 256>>>(out, tgt, rl);
    if ((long long)out_size >= (long long)BT_ * V_ + 1)
        loss_reduce_kernel<<<1, 1024>>>(rl, out + (long long)BT_ * V_);
}